// round 3
// baseline (speedup 1.0000x reference)
#include <cuda_runtime.h>
#include <cuda_bf16.h>
#include <math.h>

// ---------------------------------------------------------------------------
// Problem constants
// ---------------------------------------------------------------------------
#define BATCH 8192
#define SEQ   16
#define DIM   128
#define MTOT  (BATCH * SEQ)        // 131072 rows
#define HID   1024
#define GCN   40
#define NUMF  103
#define EPSV  1e-5f

// ---------------------------------------------------------------------------
// Scratch (device globals: the sanctioned no-alloc workaround)
// ---------------------------------------------------------------------------
__device__ float g_X[MTOT * DIM];     // layer io (xpe -> layer outputs)
__device__ float g_Qb[MTOT * DIM];    // q, then ctx (in-place)
__device__ float g_Kb[MTOT * DIM];    // k, then h
__device__ float g_Vb[MTOT * DIM];    // v
__device__ float g_F[MTOT * HID];     // ffn hidden
__device__ float g_Np[BATCH * DIM];   // num projection
__device__ float g_bnp[2 * 64 * DIM]; // BN partial sums / sumsq
__device__ float g_bns[2 * DIM];      // BN scale / shift
__device__ float g_PE[SEQ * DIM];     // positional encoding

__device__ __forceinline__ float* selbuf(int s) {
    switch (s) {
        case 0: return g_X;
        case 1: return g_Qb;
        case 2: return g_Kb;
        case 3: return g_Vb;
        case 4: return g_F;
    }
    return nullptr;
}

__device__ __forceinline__ float warp_red(float v) {
    #pragma unroll
    for (int o = 16; o; o >>= 1) v += __shfl_xor_sync(0xffffffffu, v, o);
    return v;
}

// ---------------------------------------------------------------------------
// PE init (double precision, matches reference's float64 table)
// ---------------------------------------------------------------------------
__global__ void pe_init_kernel() {
    int idx = blockIdx.x * 1024 + threadIdx.x;
    if (idx < SEQ * DIM) {
        int s = idx >> 7, d = idx & 127;
        double e = (double)((d >> 1) * 2) / (double)DIM;
        double p = (double)s / pow(10000.0, e);
        g_PE[idx] = (float)((d & 1) ? cos(p) : sin(p));
    }
}

// xpe = x + PE  (float4 vectorized)
__global__ void add_pe_kernel(const float* __restrict__ x) {
    size_t i4 = (size_t)blockIdx.x * 256 + threadIdx.x;   // 4194304 total
    float4 xv = ((const float4*)x)[i4];
    size_t e = i4 * 4;
    int sd = (int)(e & 2047);                              // (s*128 + d)
    float4 pv = *(const float4*)(g_PE + sd);
    xv.x += pv.x; xv.y += pv.y; xv.z += pv.z; xv.w += pv.w;
    ((float4*)g_X)[i4] = xv;
}

// ---------------------------------------------------------------------------
// Generic tiled GEMM: C[M,N] = A[M,K] @ W[K,N] + bias   (optional relu)
// BM=64, BN=64, BK=16, 256 threads, 4x4 per thread.
// ---------------------------------------------------------------------------
template <bool RELU>
__global__ __launch_bounds__(256) void gemm_bias_kernel(
    int asel, const float* __restrict__ W, const float* __restrict__ bias,
    int csel, int N, int Kdim)
{
    const float* A = selbuf(asel);
    float* C = selbuf(csel);

    __shared__ float As[16][68];
    __shared__ float Bs[16][64];

    int tid = threadIdx.x;
    int rb = blockIdx.x * 64;
    int nb = blockIdx.y * 64;
    int tx = tid & 15, ty = tid >> 4;       // cols tx*4.., rows ty*4..
    int ar = tid >> 2, ak = (tid & 3) * 4;  // A loader
    int bk = tid >> 4, bn = (tid & 15) * 4; // B loader

    float acc[4][4] = {};

    for (int kb = 0; kb < Kdim; kb += 16) {
        float4 av = *(const float4*)(A + (size_t)(rb + ar) * Kdim + kb + ak);
        As[ak + 0][ar] = av.x; As[ak + 1][ar] = av.y;
        As[ak + 2][ar] = av.z; As[ak + 3][ar] = av.w;
        *(float4*)&Bs[bk][bn] = *(const float4*)(W + (size_t)(kb + bk) * N + nb + bn);
        __syncthreads();
        #pragma unroll
        for (int kk = 0; kk < 16; kk++) {
            float4 a4 = *(const float4*)&As[kk][ty * 4];
            float4 b4 = *(const float4*)&Bs[kk][tx * 4];
            float a[4] = {a4.x, a4.y, a4.z, a4.w};
            float b[4] = {b4.x, b4.y, b4.z, b4.w};
            #pragma unroll
            for (int i = 0; i < 4; i++)
                #pragma unroll
                for (int j = 0; j < 4; j++)
                    acc[i][j] = fmaf(a[i], b[j], acc[i][j]);
        }
        __syncthreads();
    }

    float4 bv = *(const float4*)(bias + nb + tx * 4);
    float bb[4] = {bv.x, bv.y, bv.z, bv.w};
    #pragma unroll
    for (int i = 0; i < 4; i++) {
        float4 ov;
        float v0 = acc[i][0] + bb[0], v1 = acc[i][1] + bb[1];
        float v2 = acc[i][2] + bb[2], v3 = acc[i][3] + bb[3];
        if (RELU) {
            v0 = fmaxf(v0, 0.f); v1 = fmaxf(v1, 0.f);
            v2 = fmaxf(v2, 0.f); v3 = fmaxf(v3, 0.f);
        }
        ov.x = v0; ov.y = v1; ov.z = v2; ov.w = v3;
        *(float4*)(C + (size_t)(rb + ty * 4 + i) * N + nb + tx * 4) = ov;
    }
}

// ---------------------------------------------------------------------------
// GEMM + bias + residual + LayerNorm (N == 128, full row per block-warp)
// BM=32, BN=128, BK=16, 256 threads; each warp owns 4 full output rows.
// ---------------------------------------------------------------------------
__global__ __launch_bounds__(256) void gemm_ln_kernel(
    int asel, const float* __restrict__ W, const float* __restrict__ bias,
    int rsel, const float* __restrict__ gam, const float* __restrict__ bet,
    int csel, int Kdim)
{
    const float* A = selbuf(asel);
    const float* R = selbuf(rsel);
    float* C = selbuf(csel);

    __shared__ float As[16][36];
    __shared__ float Bs[16][128];

    int tid = threadIdx.x;
    int tx = tid & 31, ty = tid >> 5;     // tx: col group, ty: warp = 4 rows
    int rb = blockIdx.x * 32;

    float acc[4][4] = {};

    for (int kb = 0; kb < Kdim; kb += 16) {
        if (tid < 128) {
            int ar = tid >> 2, ak = (tid & 3) * 4;
            float4 av = *(const float4*)(A + (size_t)(rb + ar) * Kdim + kb + ak);
            As[ak + 0][ar] = av.x; As[ak + 1][ar] = av.y;
            As[ak + 2][ar] = av.z; As[ak + 3][ar] = av.w;
        }
        int bk = tid >> 5, bn = (tid & 31) * 4;
        *(float4*)&Bs[bk][bn]     = *(const float4*)(W + (size_t)(kb + bk) * DIM + bn);
        *(float4*)&Bs[bk + 8][bn] = *(const float4*)(W + (size_t)(kb + bk + 8) * DIM + bn);
        __syncthreads();
        #pragma unroll
        for (int kk = 0; kk < 16; kk++) {
            float4 a4 = *(const float4*)&As[kk][ty * 4];
            float4 b4 = *(const float4*)&Bs[kk][tx * 4];
            float a[4] = {a4.x, a4.y, a4.z, a4.w};
            float b[4] = {b4.x, b4.y, b4.z, b4.w};
            #pragma unroll
            for (int i = 0; i < 4; i++)
                #pragma unroll
                for (int j = 0; j < 4; j++)
                    acc[i][j] = fmaf(a[i], b[j], acc[i][j]);
        }
        __syncthreads();
    }

    // epilogue: + bias + residual, then LN over each full row (warp-wide)
    float4 bv = *(const float4*)(bias + tx * 4);
    float bb[4] = {bv.x, bv.y, bv.z, bv.w};
    float4 gv = *(const float4*)(gam + tx * 4);
    float gg[4] = {gv.x, gv.y, gv.z, gv.w};
    float4 ev = *(const float4*)(bet + tx * 4);
    float ee[4] = {ev.x, ev.y, ev.z, ev.w};

    #pragma unroll
    for (int i = 0; i < 4; i++) {
        size_t row = (size_t)(rb + ty * 4 + i);
        float4 rv = *(const float4*)(R + row * DIM + tx * 4);
        float rr[4] = {rv.x, rv.y, rv.z, rv.w};
        float s = 0.f, q = 0.f;
        #pragma unroll
        for (int j = 0; j < 4; j++) {
            float v = acc[i][j] + bb[j] + rr[j];
            acc[i][j] = v;
            s += v; q += v * v;
        }
        s = warp_red(s);
        q = warp_red(q);
        float mean = s * (1.f / 128.f);
        float var = q * (1.f / 128.f) - mean * mean;
        float rstd = rsqrtf(var + EPSV);
        float4 ov;
        ov.x = (acc[i][0] - mean) * rstd * gg[0] + ee[0];
        ov.y = (acc[i][1] - mean) * rstd * gg[1] + ee[1];
        ov.z = (acc[i][2] - mean) * rstd * gg[2] + ee[2];
        ov.w = (acc[i][3] - mean) * rstd * gg[3] + ee[3];
        *(float4*)(C + row * DIM + tx * 4) = ov;
    }
}

// ---------------------------------------------------------------------------
// Attention: one warp per unit n (65536 units). The raw .view() reshape makes
// each unit the contiguous 256-float chunk at n*256 in q/k/v. ctx written
// in-place over g_Qb.
// ---------------------------------------------------------------------------
__global__ __launch_bounds__(256) void attn_kernel() {
    __shared__ float s_q[8][256];
    __shared__ float s_k[8][256];
    __shared__ float s_v[8][256];

    int w = threadIdx.x >> 5, lane = threadIdx.x & 31;
    size_t n = (size_t)blockIdx.x * 8 + w;
    size_t base = n * 256;

    // cooperative warp load: 64 float4 per tensor
    const float4* q4 = (const float4*)(g_Qb + base);
    const float4* k4 = (const float4*)(g_Kb + base);
    const float4* v4 = (const float4*)(g_Vb + base);
    ((float4*)s_q[w])[lane]      = q4[lane];
    ((float4*)s_q[w])[lane + 32] = q4[lane + 32];
    ((float4*)s_k[w])[lane]      = k4[lane];
    ((float4*)s_k[w])[lane + 32] = k4[lane + 32];
    ((float4*)s_v[w])[lane]      = v4[lane];
    ((float4*)s_v[w])[lane + 32] = v4[lane + 32];
    __syncwarp();

    int i = lane >> 1;              // row 0..15
    int jb = (lane & 1) * 8;        // col half

    float qr[16];
    #pragma unroll
    for (int u = 0; u < 4; u++) {
        float4 t4 = *(const float4*)&s_q[w][i * 16 + u * 4];
        qr[u * 4 + 0] = t4.x; qr[u * 4 + 1] = t4.y;
        qr[u * 4 + 2] = t4.z; qr[u * 4 + 3] = t4.w;
    }

    float sc[8];
    #pragma unroll
    for (int j = 0; j < 8; j++) {
        const float* kr = &s_k[w][(jb + j) * 16];
        float d = 0.f;
        #pragma unroll
        for (int u = 0; u < 16; u++) d = fmaf(qr[u], kr[u], d);
        sc[j] = d * 0.25f;          // DH^-0.5 = 1/4
    }

    float mx = sc[0];
    #pragma unroll
    for (int j = 1; j < 8; j++) mx = fmaxf(mx, sc[j]);
    mx = fmaxf(mx, __shfl_xor_sync(0xffffffffu, mx, 1));

    float sum = 0.f;
    #pragma unroll
    for (int j = 0; j < 8; j++) { sc[j] = __expf(sc[j] - mx); sum += sc[j]; }
    sum += __shfl_xor_sync(0xffffffffu, sum, 1);
    float inv = 1.f / sum;

    float acc[16] = {};
    #pragma unroll
    for (int j = 0; j < 8; j++) {
        float p = sc[j] * inv;
        const float* vr = &s_v[w][(jb + j) * 16];
        #pragma unroll
        for (int u = 0; u < 16; u++) acc[u] = fmaf(p, vr[u], acc[u]);
    }
    #pragma unroll
    for (int u = 0; u < 16; u++)
        acc[u] += __shfl_xor_sync(0xffffffffu, acc[u], 1);

    int db = (lane & 1) * 8;
    float* op = g_Qb + base + i * 16 + db;
    *(float4*)op       = make_float4(acc[db + 0], acc[db + 1], acc[db + 2], acc[db + 3]);
    *(float4*)(op + 4) = make_float4(acc[db + 4], acc[db + 5], acc[db + 6], acc[db + 7]);
}

// ---------------------------------------------------------------------------
// Head: num projection  n = num @ Wn + bnum   (one row per 128-thread block)
// ---------------------------------------------------------------------------
__global__ __launch_bounds__(128) void numproj_kernel(
    const float* __restrict__ num, const float* __restrict__ Wn,
    const float* __restrict__ bnum)
{
    __shared__ float sn[NUMF];
    int b = blockIdx.x, t = threadIdx.x;
    if (t < NUMF) sn[t] = num[(size_t)b * NUMF + t];
    __syncthreads();
    float acc = bnum[t];
    #pragma unroll 1
    for (int k = 0; k < NUMF; k++)
        acc = fmaf(sn[k], Wn[k * DIM + t], acc);
    g_Np[(size_t)b * DIM + t] = acc;
}

// BN stats pass 1: 64 blocks, each reduces 128 rows
__global__ __launch_bounds__(256) void bn_partial_kernel() {
    int j = blockIdx.x, t = threadIdx.x;
    int col = t & 127, half = t >> 7;
    float s = 0.f, q = 0.f;
    for (int i = 0; i < 64; i++) {
        float v = g_Np[(size_t)(j * 128 + half * 64 + i) * DIM + col];
        s += v; q += v * v;
    }
    __shared__ float ss[256], sq[256];
    ss[t] = s; sq[t] = q;
    __syncthreads();
    if (half == 0) {
        g_bnp[j * DIM + col]            = ss[t] + ss[t + 128];
        g_bnp[64 * DIM + j * DIM + col] = sq[t] + sq[t + 128];
    }
}

// BN stats pass 2: fold to per-column scale/shift
__global__ __launch_bounds__(128) void bn_final_kernel(
    const float* __restrict__ gamma, const float* __restrict__ beta)
{
    int c = threadIdx.x;
    float s = 0.f, q = 0.f;
    for (int j = 0; j < 64; j++) {
        s += g_bnp[j * DIM + c];
        q += g_bnp[64 * DIM + j * DIM + c];
    }
    float mu = s * (1.f / 8192.f);
    float var = q * (1.f / 8192.f) - mu * mu;
    float a = gamma[c] * rsqrtf(var + EPSV);
    g_bns[c] = a;
    g_bns[DIM + c] = beta[c] - mu * a;
}

// Final head: sigmoid(flat.Wf + gcn.Wf + bn(n).Wf + bf), one block per batch row
__global__ __launch_bounds__(256) void final_kernel(
    const float* __restrict__ gcn, const float* __restrict__ Wf,
    const float* __restrict__ bf, float* __restrict__ out)
{
    int b = blockIdx.x, t = threadIdx.x;
    const float* xr = g_X + (size_t)b * (SEQ * DIM);
    float acc = 0.f;
    #pragma unroll
    for (int i = 0; i < 8; i++) {
        int idx = t + 256 * i;
        acc = fmaf(xr[idx], Wf[idx], acc);
    }
    if (t < GCN)
        acc = fmaf(gcn[(size_t)b * GCN + t], Wf[SEQ * DIM + t], acc);
    if (t < DIM) {
        float v = g_Np[(size_t)b * DIM + t] * g_bns[t] + g_bns[DIM + t];
        acc = fmaf(v, Wf[SEQ * DIM + GCN + t], acc);
    }
    acc = warp_red(acc);
    __shared__ float red[8];
    if ((t & 31) == 0) red[t >> 5] = acc;
    __syncthreads();
    if (t == 0) {
        float z = red[0] + red[1] + red[2] + red[3]
                + red[4] + red[5] + red[6] + red[7] + bf[0];
        out[b] = 1.f / (1.f + expf(-z));
    }
}

// ---------------------------------------------------------------------------
// Launch: full pipeline, graph-capturable (kernel launches only)
// ---------------------------------------------------------------------------
extern "C" void kernel_launch(void* const* d_in, const int* in_sizes, int n_in,
                              void* d_out, int out_size)
{
    const float* x    = (const float*)d_in[0];
    const float* gcn  = (const float*)d_in[1];
    const float* num  = (const float*)d_in[2];
    const float* Wq   = (const float*)d_in[3];
    const float* bq   = (const float*)d_in[4];
    const float* Wk   = (const float*)d_in[5];
    const float* bk   = (const float*)d_in[6];
    const float* Wv   = (const float*)d_in[7];
    const float* bv   = (const float*)d_in[8];
    const float* Wo   = (const float*)d_in[9];
    const float* bo   = (const float*)d_in[10];
    const float* ln1g = (const float*)d_in[11];
    const float* ln1b = (const float*)d_in[12];
    const float* W1   = (const float*)d_in[13];
    const float* b1   = (const float*)d_in[14];
    const float* W2   = (const float*)d_in[15];
    const float* b2   = (const float*)d_in[16];
    const float* ln2g = (const float*)d_in[17];
    const float* ln2b = (const float*)d_in[18];
    const float* Wn   = (const float*)d_in[19];
    const float* bnum = (const float*)d_in[20];
    const float* bng  = (const float*)d_in[21];
    const float* bnb  = (const float*)d_in[22];
    const float* Wf   = (const float*)d_in[23];
    const float* bf   = (const float*)d_in[24];
    float* out = (float*)d_out;

    pe_init_kernel<<<2, 1024>>>();
    add_pe_kernel<<<16384, 256>>>(x);

    for (int l = 0; l < 2; l++) {
        const int wOff = l * DIM * DIM;       // 16384
        const int fOff = l * DIM * HID;       // 131072
        // QKV projections: X -> Q, K, V
        gemm_bias_kernel<false><<<dim3(MTOT / 64, 2), 256>>>(0, Wq + wOff, bq + l * DIM, 1, DIM, DIM);
        gemm_bias_kernel<false><<<dim3(MTOT / 64, 2), 256>>>(0, Wk + wOff, bk + l * DIM, 2, DIM, DIM);
        gemm_bias_kernel<false><<<dim3(MTOT / 64, 2), 256>>>(0, Wv + wOff, bv + l * DIM, 3, DIM, DIM);
        // attention (ctx -> g_Qb in place)
        attn_kernel<<<MTOT * 8 / 16 / 8, 256>>>();   // 65536 warps / 8 per block = 8192
        // h = LN(ctx @ Wo + bo + X)  -> g_Kb
        gemm_ln_kernel<<<MTOT / 32, 256>>>(1, Wo + wOff, bo + l * DIM, 0,
                                           ln1g + l * DIM, ln1b + l * DIM, 2, DIM);
        // ffn hidden = relu(h @ W1 + b1) -> g_F
        gemm_bias_kernel<true><<<dim3(MTOT / 64, HID / 64), 256>>>(2, W1 + fOff, b1 + l * HID, 4, HID, DIM);
        // out = LN(ffn @ W2 + b2 + h) -> g_X
        gemm_ln_kernel<<<MTOT / 32, 256>>>(4, W2 + fOff, b2 + l * DIM, 2,
                                           ln2g + l * DIM, ln2b + l * DIM, 0, HID);
    }

    numproj_kernel<<<BATCH, 128>>>(num, Wn, bnum);
    bn_partial_kernel<<<64, 256>>>();
    bn_final_kernel<<<1, 128>>>(bng, bnb);
    final_kernel<<<BATCH, 256>>>(gcn, Wf, bf, out);
}

// round 7
// speedup vs baseline: 2.1342x; 2.1342x over previous
#include <cuda_runtime.h>
#include <cuda_bf16.h>
#include <math.h>
#include <stdint.h>

// ---------------------------------------------------------------------------
// Problem constants
// ---------------------------------------------------------------------------
#define BATCH 8192
#define SEQ   16
#define DIM   128
#define MTOT  (BATCH * SEQ)        // 131072 rows
#define HID   1024
#define GCN   40
#define NUMF  103
#define EPSV  1e-5f

// Weight-tile store: each "slot" = one 128(N)x64(K) tile, hi then lo bf16,
// in MMA-ready SW128-swizzled layout (128B rows, k-contiguous). 8192 bf16/half.
#define SLOT_BF16   16384            // hi(8192) + lo(8192)
#define SLOTS_TOTAL 80               // 40 per layer x 2 layers
// per-layer slot map: Wq:0-1 Wk:2-3 Wv:4-5 Wo:6-7 W1:8-23([nb][kc]) W2:24-39

// Dynamic smem: 1KB align slack + max(stage 64KB, C-stage 128*132*4)
#define STAGE_BYTES 65536
#define CST_BYTES   (128 * 132 * 4)       // 67584
#define DSMEM_BYTES (1024 + CST_BYTES)    // 68608

// stage offsets
#define OA_HI 0u
#define OA_LO 16384u
#define OB_HI 32768u
#define OB_LO 49152u

// ---------------------------------------------------------------------------
// Scratch (device globals: the sanctioned no-alloc workaround)
// ---------------------------------------------------------------------------
__device__ float g_X[MTOT * DIM];
__device__ float g_Qb[MTOT * DIM];
__device__ float g_Kb[MTOT * DIM];
__device__ float g_Vb[MTOT * DIM];
__device__ float g_F[MTOT * HID];
__device__ float g_Np[BATCH * DIM];
__device__ float g_bnp[2 * 64 * DIM];
__device__ float g_bns[2 * DIM];
__device__ float g_PE[SEQ * DIM];
__device__ __nv_bfloat16 g_Wt[(size_t)SLOTS_TOTAL * SLOT_BF16];

__device__ __forceinline__ float* selbuf(int s) {
    switch (s) {
        case 0: return g_X;
        case 1: return g_Qb;
        case 2: return g_Kb;
        case 3: return g_Vb;
        case 4: return g_F;
    }
    return nullptr;
}

__device__ __forceinline__ float warp_red(float v) {
    #pragma unroll
    for (int o = 16; o; o >>= 1) v += __shfl_xor_sync(0xffffffffu, v, o);
    return v;
}

// ---------------------------------------------------------------------------
// PTX helpers (family-target-safe: ldmatrix sm_75+, mma.sync bf16 sm_80+)
// ---------------------------------------------------------------------------
__device__ __forceinline__ uint32_t smem_u32(const void* p) {
    uint32_t a;
    asm("{ .reg .u64 t; cvta.to.shared.u64 t, %1; cvt.u32.u64 %0, t; }"
        : "=r"(a) : "l"(p));
    return a;
}

__device__ __forceinline__ void ldm4(uint32_t* r, uint32_t addr) {
    asm volatile("ldmatrix.sync.aligned.m8n8.x4.shared.b16 {%0,%1,%2,%3}, [%4];"
                 : "=r"(r[0]), "=r"(r[1]), "=r"(r[2]), "=r"(r[3]) : "r"(addr));
}

__device__ __forceinline__ void mma16816(float* c, const uint32_t* a,
                                         const uint32_t* b) {
    asm volatile(
        "mma.sync.aligned.m16n8k16.row.col.f32.bf16.bf16.f32 "
        "{%0,%1,%2,%3}, {%4,%5,%6,%7}, {%8,%9}, {%0,%1,%2,%3};"
        : "+f"(c[0]), "+f"(c[1]), "+f"(c[2]), "+f"(c[3])
        : "r"(a[0]), "r"(a[1]), "r"(a[2]), "r"(a[3]), "r"(b[0]), "r"(b[1]));
}

__device__ __forceinline__ uint32_t sw128(uint32_t off) {
    return off ^ ((off >> 3) & 0x70);
}

// split fp32 pair -> packed bf16x2 hi + lo
__device__ __forceinline__ uint32_t split2(float a, float b, uint32_t& lo_out) {
    __nv_bfloat16 ha = __float2bfloat16(a);
    __nv_bfloat16 hb = __float2bfloat16(b);
    __nv_bfloat16 la = __float2bfloat16(a - __bfloat162float(ha));
    __nv_bfloat16 lb = __float2bfloat16(b - __bfloat162float(hb));
    lo_out = (uint32_t)__bfloat16_as_ushort(la) |
             ((uint32_t)__bfloat16_as_ushort(lb) << 16);
    return (uint32_t)__bfloat16_as_ushort(ha) |
           ((uint32_t)__bfloat16_as_ushort(hb) << 16);
}

// ---------------------------------------------------------------------------
// PE init + add
// ---------------------------------------------------------------------------
__global__ void pe_init_kernel() {
    int idx = blockIdx.x * 1024 + threadIdx.x;
    if (idx < SEQ * DIM) {
        int s = idx >> 7, d = idx & 127;
        double e = (double)((d >> 1) * 2) / (double)DIM;
        double p = (double)s / pow(10000.0, e);
        g_PE[idx] = (float)((d & 1) ? cos(p) : sin(p));
    }
}

__global__ void add_pe_kernel(const float* __restrict__ x) {
    size_t i4 = (size_t)blockIdx.x * 256 + threadIdx.x;
    float4 xv = ((const float4*)x)[i4];
    int sd = (int)((i4 * 4) & 2047);
    float4 pv = *(const float4*)(g_PE + sd);
    xv.x += pv.x; xv.y += pv.y; xv.z += pv.z; xv.w += pv.w;
    ((float4*)g_X)[i4] = xv;
}

// ---------------------------------------------------------------------------
// Weight prep: transpose + split + swizzle into MMA-ready tiles.
// tile[n_local][k_local] = W[k][n] (bf16 hi/lo), byte_off = n*128 + k*2, SW128.
// This is exactly the non-trans ldmatrix layout for the B (col-major) operand.
// ---------------------------------------------------------------------------
__global__ __launch_bounds__(256) void prep_weights_kernel(
    const float* __restrict__ Wq, const float* __restrict__ Wk,
    const float* __restrict__ Wv, const float* __restrict__ Wo,
    const float* __restrict__ W1, const float* __restrict__ W2)
{
    int slot = blockIdx.x;
    int l = slot / 40, s = slot % 40;
    const float* W; int Nmat, nb, kc;
    if (s < 8) {
        int m = s >> 1; kc = s & 1; nb = 0; Nmat = 128;
        const float* mats[4] = {Wq, Wk, Wv, Wo};
        W = mats[m] + (size_t)l * DIM * DIM;
    } else if (s < 24) {
        int t = s - 8; nb = t >> 1; kc = t & 1; Nmat = HID;
        W = W1 + (size_t)l * DIM * HID;
    } else {
        int t = s - 24; nb = 0; kc = t; Nmat = 128;
        W = W2 + (size_t)l * HID * DIM;
    }
    char* tile_hi = (char*)(g_Wt + (size_t)slot * SLOT_BF16);
    char* tile_lo = tile_hi + 16384;

    for (int it = 0; it < 4; it++) {
        int g = it * 256 + threadIdx.x;           // 16B granule id 0..1023
        int n_local = g >> 3;
        int kq = (g & 7) * 8;                      // k_local base (8 bf16)
        uint4 hi4, lo4;
        uint32_t* hp = (uint32_t*)&hi4;
        uint32_t* lp = (uint32_t*)&lo4;
        #pragma unroll
        for (int u = 0; u < 4; u++) {
            float v0 = W[(size_t)(kc * 64 + kq + u * 2 + 0) * Nmat + nb * 128 + n_local];
            float v1 = W[(size_t)(kc * 64 + kq + u * 2 + 1) * Nmat + nb * 128 + n_local];
            hp[u] = split2(v0, v1, lp[u]);
        }
        uint32_t sw = sw128((uint32_t)(n_local * 128 + kq * 2));
        *(uint4*)(tile_hi + sw) = hi4;
        *(uint4*)(tile_lo + sw) = lo4;
    }
}

// ---------------------------------------------------------------------------
// mma.sync GEMM core: C_tile[128,128] = epi(A[rb:rb+128,:] @ W + bias ...)
// 8 warps: warp_m = wid&1 (64 rows), warp_n = wid>>1 (32 cols).
// 3-product split-bf16: Ahi*Bhi + Ahi*Blo + Alo*Bhi  (~fp32 accuracy).
// EPI: 0 = bias, 1 = bias+relu, 2 = bias+residual+LayerNorm
// ---------------------------------------------------------------------------
template <int EPI>
__device__ __forceinline__ void gemm_core(
    char* dsm_raw,
    const float* __restrict__ A, int lda,
    const __nv_bfloat16* __restrict__ Wslots, int nchunks,
    const float* __restrict__ bias,
    const float* __restrict__ R,
    const float* __restrict__ gam, const float* __restrict__ bet,
    float* __restrict__ C, int ldc, int ncoloff, int rb)
{
    uint32_t raw_u = smem_u32(dsm_raw);
    uint32_t sbase = (raw_u + 1023) & ~1023u;
    char* dsm = dsm_raw + (sbase - raw_u);

    int tid = threadIdx.x;
    int wid = tid >> 5, lane = tid & 31;
    int wm = wid & 1, wn = wid >> 1;

    // per-lane ldmatrix geometry
    int mt = lane >> 3;                       // matrix id 0..3
    int rr = lane & 7;
    int row_off = ((mt & 1) << 3) + rr;       // +0/+8 within 16
    int kk_off = (mt >> 1) << 3;              // +0/+8 within 16

    float acc[4][4][4];
    #pragma unroll
    for (int i = 0; i < 4; i++)
        #pragma unroll
        for (int j = 0; j < 4; j++)
            #pragma unroll
            for (int r = 0; r < 4; r++) acc[i][j][r] = 0.f;

    for (int c = 0; c < nchunks; c++) {
        // ---- load chunk: A fp32 -> split bf16 hi/lo (swizzled); B copy ----
        #pragma unroll
        for (int p = 0; p < 8; p++) {
            int i = p * 256 + tid;                 // float4 id 0..2047
            int arow = i >> 4, c4 = i & 15;
            float4 v = *(const float4*)(A + (size_t)(rb + arow) * lda + c * 64 + c4 * 4);
            uint2 hi2, lo2;
            hi2.x = split2(v.x, v.y, lo2.x);
            hi2.y = split2(v.z, v.w, lo2.y);
            uint32_t sw = sw128((uint32_t)(arow * 128 + c4 * 8));
            *(uint2*)(dsm + OA_HI + sw) = hi2;
            *(uint2*)(dsm + OA_LO + sw) = lo2;
        }
        {
            const uint4* sh = (const uint4*)(Wslots + (size_t)c * SLOT_BF16);
            const uint4* sl = sh + 1024;
            #pragma unroll
            for (int p = 0; p < 4; p++) {
                int i = p * 256 + tid;
                *(uint4*)(dsm + OB_HI + i * 16) = sh[i];
                *(uint4*)(dsm + OB_LO + i * 16) = sl[i];
            }
        }
        __syncthreads();

        // ---- compute: 4 k16 steps ----
        #pragma unroll
        for (int k16 = 0; k16 < 4; k16++) {
            int kbase = k16 * 16 + kk_off;
            uint32_t bh[4][2], bl[4][2];
            #pragma unroll
            for (int in2 = 0; in2 < 2; in2++) {
                int nrow = wn * 32 + in2 * 16 + row_off;
                uint32_t off = sw128((uint32_t)(nrow * 128 + kbase * 2));
                uint32_t t[4];
                ldm4(t, sbase + OB_HI + off);
                bh[in2 * 2 + 0][0] = t[0]; bh[in2 * 2 + 0][1] = t[2];
                bh[in2 * 2 + 1][0] = t[1]; bh[in2 * 2 + 1][1] = t[3];
                ldm4(t, sbase + OB_LO + off);
                bl[in2 * 2 + 0][0] = t[0]; bl[in2 * 2 + 0][1] = t[2];
                bl[in2 * 2 + 1][0] = t[1]; bl[in2 * 2 + 1][1] = t[3];
            }
            #pragma unroll
            for (int im = 0; im < 4; im++) {
                int mrow = wm * 64 + im * 16 + row_off;
                uint32_t off = sw128((uint32_t)(mrow * 128 + kbase * 2));
                uint32_t ah[4], al[4];
                ldm4(ah, sbase + OA_HI + off);
                ldm4(al, sbase + OA_LO + off);
                #pragma unroll
                for (int in = 0; in < 4; in++) {
                    mma16816(acc[im][in], ah, bh[in]);
                    mma16816(acc[im][in], ah, bl[in]);
                    mma16816(acc[im][in], al, bh[in]);
                }
            }
        }
        __syncthreads();
    }

    // ---- epilogue ----
    int r_in = lane >> 2;                 // 0..7
    int c_in = (lane & 3) * 2;

    if (EPI != 2) {
        #pragma unroll
        for (int im = 0; im < 4; im++) {
            size_t r0 = (size_t)(rb + wm * 64 + im * 16 + r_in);
            #pragma unroll
            for (int in = 0; in < 4; in++) {
                int cl = wn * 32 + in * 8 + c_in;
                float b0 = bias[cl], b1 = bias[cl + 1];
                float v0 = acc[im][in][0] + b0, v1 = acc[im][in][1] + b1;
                float v2 = acc[im][in][2] + b0, v3 = acc[im][in][3] + b1;
                if (EPI == 1) {
                    v0 = fmaxf(v0, 0.f); v1 = fmaxf(v1, 0.f);
                    v2 = fmaxf(v2, 0.f); v3 = fmaxf(v3, 0.f);
                }
                *(float2*)(C + r0 * ldc + ncoloff + cl) = make_float2(v0, v1);
                *(float2*)(C + (r0 + 8) * ldc + ncoloff + cl) = make_float2(v2, v3);
            }
        }
    } else {
        // stage C (+bias+residual) into padded smem, then LN per row
        float* Cst = (float*)dsm;         // [128][132]
        __shared__ float s_mean[128], s_rstd[128];
        #pragma unroll
        for (int im = 0; im < 4; im++) {
            int r0 = wm * 64 + im * 16 + r_in;
            size_t gr0 = (size_t)(rb + r0);
            #pragma unroll
            for (int in = 0; in < 4; in++) {
                int cl = wn * 32 + in * 8 + c_in;
                float b0 = bias[cl], b1 = bias[cl + 1];
                float2 rv0 = *(const float2*)(R + gr0 * DIM + cl);
                float2 rv1 = *(const float2*)(R + (gr0 + 8) * DIM + cl);
                Cst[r0 * 132 + cl]           = acc[im][in][0] + b0 + rv0.x;
                Cst[r0 * 132 + cl + 1]       = acc[im][in][1] + b1 + rv0.y;
                Cst[(r0 + 8) * 132 + cl]     = acc[im][in][2] + b0 + rv1.x;
                Cst[(r0 + 8) * 132 + cl + 1] = acc[im][in][3] + b1 + rv1.y;
            }
        }
        __syncthreads();
        if (tid < 128) {
            const float* rp = Cst + tid * 132;
            float s = 0.f, q = 0.f;
            #pragma unroll
            for (int j4 = 0; j4 < 32; j4++) {
                float4 v = *(const float4*)(rp + j4 * 4);
                s += v.x + v.y + v.z + v.w;
                q += v.x * v.x + v.y * v.y + v.z * v.z + v.w * v.w;
            }
            float mean = s * (1.f / 128.f);
            float var = q * (1.f / 128.f) - mean * mean;
            s_mean[tid] = mean;
            s_rstd[tid] = rsqrtf(var + EPSV);
        }
        __syncthreads();
        #pragma unroll
        for (int it = 0; it < 16; it++) {
            int idx = it * 256 + tid;
            int row = idx >> 5, q4 = (idx & 31) * 4;
            float m = s_mean[row], rs = s_rstd[row];
            float4 v = *(const float4*)(Cst + row * 132 + q4);
            float4 gv = *(const float4*)(gam + q4);
            float4 ev = *(const float4*)(bet + q4);
            float4 o;
            o.x = (v.x - m) * rs * gv.x + ev.x;
            o.y = (v.y - m) * rs * gv.y + ev.y;
            o.z = (v.z - m) * rs * gv.z + ev.z;
            o.w = (v.w - m) * rs * gv.w + ev.w;
            *(float4*)(C + (size_t)(rb + row) * ldc + q4) = o;
        }
    }
}

// Generic GEMM kernel: blockIdx.x = output col block, blockIdx.y = row block
template <int EPI>
__global__ __launch_bounds__(256, 2) void gemm_tc_kernel(
    int asel, int lda, int slotbase, int kchunks,
    const float* __restrict__ bias, int rsel,
    const float* __restrict__ gam, const float* __restrict__ bet,
    int csel, int ldc)
{
    extern __shared__ char dsm[];
    int nb = blockIdx.x;
    int rb = blockIdx.y * 128;
    const __nv_bfloat16* Ws =
        g_Wt + ((size_t)slotbase + (size_t)nb * kchunks) * SLOT_BF16;
    gemm_core<EPI>(dsm, selbuf(asel), lda, Ws, kchunks,
                   bias + nb * 128,
                   rsel >= 0 ? selbuf(rsel) : nullptr, gam, bet,
                   selbuf(csel), ldc, nb * 128, rb);
}

// QKV fused launch: blockIdx.x selects q/k/v (co-scheduled -> A tile L2 reuse)
__global__ __launch_bounds__(256, 2) void qkv_tc_kernel(
    int lslot, const float* __restrict__ bq,
    const float* __restrict__ bk, const float* __restrict__ bv)
{
    extern __shared__ char dsm[];
    int which = blockIdx.x;
    int rb = blockIdx.y * 128;
    const __nv_bfloat16* Ws = g_Wt + (size_t)(lslot + which * 2) * SLOT_BF16;
    const float* bias = (which == 0) ? bq : (which == 1) ? bk : bv;
    float* C = (which == 0) ? g_Qb : (which == 1) ? g_Kb : g_Vb;
    gemm_core<0>(dsm, g_X, DIM, Ws, 2, bias, nullptr, nullptr, nullptr,
                 C, DIM, 0, rb);
}

// ---------------------------------------------------------------------------
// Attention: one warp per 16x16 unit (raw .view() => contiguous 256-fl chunk)
// ---------------------------------------------------------------------------
__global__ __launch_bounds__(256) void attn_kernel() {
    __shared__ float s_q[8][256];
    __shared__ float s_k[8][256];
    __shared__ float s_v[8][256];

    int w = threadIdx.x >> 5, lane = threadIdx.x & 31;
    size_t n = (size_t)blockIdx.x * 8 + w;
    size_t bse = n * 256;

    const float4* q4 = (const float4*)(g_Qb + bse);
    const float4* k4 = (const float4*)(g_Kb + bse);
    const float4* v4 = (const float4*)(g_Vb + bse);
    ((float4*)s_q[w])[lane]      = q4[lane];
    ((float4*)s_q[w])[lane + 32] = q4[lane + 32];
    ((float4*)s_k[w])[lane]      = k4[lane];
    ((float4*)s_k[w])[lane + 32] = k4[lane + 32];
    ((float4*)s_v[w])[lane]      = v4[lane];
    ((float4*)s_v[w])[lane + 32] = v4[lane + 32];
    __syncwarp();

    int i = lane >> 1;
    int jb = (lane & 1) * 8;

    float qr[16];
    #pragma unroll
    for (int u = 0; u < 4; u++) {
        float4 t4 = *(const float4*)&s_q[w][i * 16 + u * 4];
        qr[u * 4 + 0] = t4.x; qr[u * 4 + 1] = t4.y;
        qr[u * 4 + 2] = t4.z; qr[u * 4 + 3] = t4.w;
    }

    float sc[8];
    #pragma unroll
    for (int j = 0; j < 8; j++) {
        const float* kr = &s_k[w][(jb + j) * 16];
        float dd = 0.f;
        #pragma unroll
        for (int u = 0; u < 16; u++) dd = fmaf(qr[u], kr[u], dd);
        sc[j] = dd * 0.25f;
    }

    float mx = sc[0];
    #pragma unroll
    for (int j = 1; j < 8; j++) mx = fmaxf(mx, sc[j]);
    mx = fmaxf(mx, __shfl_xor_sync(0xffffffffu, mx, 1));

    float sum = 0.f;
    #pragma unroll
    for (int j = 0; j < 8; j++) { sc[j] = __expf(sc[j] - mx); sum += sc[j]; }
    sum += __shfl_xor_sync(0xffffffffu, sum, 1);
    float inv = 1.f / sum;

    float acc[16] = {};
    #pragma unroll
    for (int j = 0; j < 8; j++) {
        float p = sc[j] * inv;
        const float* vr = &s_v[w][(jb + j) * 16];
        #pragma unroll
        for (int u = 0; u < 16; u++) acc[u] = fmaf(p, vr[u], acc[u]);
    }
    #pragma unroll
    for (int u = 0; u < 16; u++)
        acc[u] += __shfl_xor_sync(0xffffffffu, acc[u], 1);

    int db = (lane & 1) * 8;
    float* op = g_Qb + bse + i * 16 + db;
    *(float4*)op       = make_float4(acc[db + 0], acc[db + 1], acc[db + 2], acc[db + 3]);
    *(float4*)(op + 4) = make_float4(acc[db + 4], acc[db + 5], acc[db + 6], acc[db + 7]);
}

// ---------------------------------------------------------------------------
// Head
// ---------------------------------------------------------------------------
__global__ __launch_bounds__(128) void numproj_kernel(
    const float* __restrict__ num, const float* __restrict__ Wn,
    const float* __restrict__ bnum)
{
    __shared__ float sn[NUMF];
    int b = blockIdx.x, t = threadIdx.x;
    if (t < NUMF) sn[t] = num[(size_t)b * NUMF + t];
    __syncthreads();
    float acc = bnum[t];
    #pragma unroll 1
    for (int k = 0; k < NUMF; k++)
        acc = fmaf(sn[k], Wn[k * DIM + t], acc);
    g_Np[(size_t)b * DIM + t] = acc;
}

__global__ __launch_bounds__(256) void bn_partial_kernel() {
    int j = blockIdx.x, t = threadIdx.x;
    int col = t & 127, half = t >> 7;
    float s = 0.f, q = 0.f;
    for (int i = 0; i < 64; i++) {
        float v = g_Np[(size_t)(j * 128 + half * 64 + i) * DIM + col];
        s += v; q += v * v;
    }
    __shared__ float ss[256], sq[256];
    ss[t] = s; sq[t] = q;
    __syncthreads();
    if (half == 0) {
        g_bnp[j * DIM + col]            = ss[t] + ss[t + 128];
        g_bnp[64 * DIM + j * DIM + col] = sq[t] + sq[t + 128];
    }
}

__global__ __launch_bounds__(128) void bn_final_kernel(
    const float* __restrict__ gamma, const float* __restrict__ beta)
{
    int c = threadIdx.x;
    float s = 0.f, q = 0.f;
    for (int j = 0; j < 64; j++) {
        s += g_bnp[j * DIM + c];
        q += g_bnp[64 * DIM + j * DIM + c];
    }
    float mu = s * (1.f / 8192.f);
    float var = q * (1.f / 8192.f) - mu * mu;
    float a = gamma[c] * rsqrtf(var + EPSV);
    g_bns[c] = a;
    g_bns[DIM + c] = beta[c] - mu * a;
}

__global__ __launch_bounds__(256) void final_kernel(
    const float* __restrict__ gcn, const float* __restrict__ Wf,
    const float* __restrict__ bf, float* __restrict__ out)
{
    int b = blockIdx.x, t = threadIdx.x;
    const float* xr = g_X + (size_t)b * (SEQ * DIM);
    float acc = 0.f;
    #pragma unroll
    for (int i = 0; i < 8; i++) {
        int idx = t + 256 * i;
        acc = fmaf(xr[idx], Wf[idx], acc);
    }
    if (t < GCN)
        acc = fmaf(gcn[(size_t)b * GCN + t], Wf[SEQ * DIM + t], acc);
    if (t < DIM) {
        float v = g_Np[(size_t)b * DIM + t] * g_bns[t] + g_bns[DIM + t];
        acc = fmaf(v, Wf[SEQ * DIM + GCN + t], acc);
    }
    acc = warp_red(acc);
    __shared__ float red[8];
    if ((t & 31) == 0) red[t >> 5] = acc;
    __syncthreads();
    if (t == 0) {
        float z = red[0] + red[1] + red[2] + red[3]
                + red[4] + red[5] + red[6] + red[7] + bf[0];
        out[b] = 1.f / (1.f + expf(-z));
    }
}

// ---------------------------------------------------------------------------
// Launch
// ---------------------------------------------------------------------------
extern "C" void kernel_launch(void* const* d_in, const int* in_sizes, int n_in,
                              void* d_out, int out_size)
{
    const float* x    = (const float*)d_in[0];
    const float* gcn  = (const float*)d_in[1];
    const float* num  = (const float*)d_in[2];
    const float* Wq   = (const float*)d_in[3];
    const float* bq   = (const float*)d_in[4];
    const float* Wk   = (const float*)d_in[5];
    const float* bk   = (const float*)d_in[6];
    const float* Wv   = (const float*)d_in[7];
    const float* bv   = (const float*)d_in[8];
    const float* Wo   = (const float*)d_in[9];
    const float* bo   = (const float*)d_in[10];
    const float* ln1g = (const float*)d_in[11];
    const float* ln1b = (const float*)d_in[12];
    const float* W1   = (const float*)d_in[13];
    const float* b1   = (const float*)d_in[14];
    const float* W2   = (const float*)d_in[15];
    const float* b2   = (const float*)d_in[16];
    const float* ln2g = (const float*)d_in[17];
    const float* ln2b = (const float*)d_in[18];
    const float* Wn   = (const float*)d_in[19];
    const float* bnum = (const float*)d_in[20];
    const float* bng  = (const float*)d_in[21];
    const float* bnb  = (const float*)d_in[22];
    const float* Wf   = (const float*)d_in[23];
    const float* bf   = (const float*)d_in[24];
    float* out = (float*)d_out;

    cudaFuncSetAttribute(qkv_tc_kernel,
        cudaFuncAttributeMaxDynamicSharedMemorySize, DSMEM_BYTES);
    cudaFuncSetAttribute(gemm_tc_kernel<1>,
        cudaFuncAttributeMaxDynamicSharedMemorySize, DSMEM_BYTES);
    cudaFuncSetAttribute(gemm_tc_kernel<2>,
        cudaFuncAttributeMaxDynamicSharedMemorySize, DSMEM_BYTES);

    pe_init_kernel<<<2, 1024>>>();
    prep_weights_kernel<<<SLOTS_TOTAL, 256>>>(Wq, Wk, Wv, Wo, W1, W2);
    add_pe_kernel<<<16384, 256>>>(x);

    for (int l = 0; l < 2; l++) {
        int lb = l * 40;
        // QKV: X -> Q(g_Qb), K(g_Kb), V(g_Vb)
        qkv_tc_kernel<<<dim3(3, MTOT / 128), 256, DSMEM_BYTES>>>(
            lb, bq + l * DIM, bk + l * DIM, bv + l * DIM);
        // attention (ctx -> g_Qb in place)
        attn_kernel<<<MTOT * 8 / 16 / 8, 256>>>();
        // h = LN(ctx @ Wo + bo + X) -> g_Kb
        gemm_tc_kernel<2><<<dim3(1, MTOT / 128), 256, DSMEM_BYTES>>>(
            1, DIM, lb + 6, 2, bo + l * DIM, 0,
            ln1g + l * DIM, ln1b + l * DIM, 2, DIM);
        // ffn hidden = relu(h @ W1 + b1) -> g_F
        gemm_tc_kernel<1><<<dim3(8, MTOT / 128), 256, DSMEM_BYTES>>>(
            2, DIM, lb + 8, 2, b1 + l * HID, -1, nullptr, nullptr, 4, HID);
        // out = LN(ffn @ W2 + b2 + h) -> g_X
        gemm_tc_kernel<2><<<dim3(1, MTOT / 128), 256, DSMEM_BYTES>>>(
            4, HID, lb + 24, 16, b2 + l * DIM, 2,
            ln2g + l * DIM, ln2b + l * DIM, 0, DIM);
    }

    numproj_kernel<<<BATCH, 128>>>(num, Wn, bnum);
    bn_partial_kernel<<<64, 256>>>();
    bn_final_kernel<<<1, 128>>>(bng, bnb);
    final_kernel<<<BATCH, 256>>>(gcn, Wf, bf, out);
}

// round 8
// speedup vs baseline: 2.3060x; 1.0805x over previous
#include <cuda_runtime.h>
#include <cuda_bf16.h>
#include <math.h>
#include <stdint.h>

// ---------------------------------------------------------------------------
// Problem constants
// ---------------------------------------------------------------------------
#define BATCH 8192
#define SEQ   16
#define DIM   128
#define MTOT  (BATCH * SEQ)        // 131072 rows
#define HID   1024
#define GCN   40
#define NUMF  103
#define EPSV  1e-5f

// Weight-tile store: each "slot" = one 128(N)x64(K) tile, hi then lo bf16,
// SW128-swizzled (128B rows, k-contiguous) — ldmatrix-ready.
#define SLOT_BF16   16384            // hi(8192) + lo(8192)
#define SLOTS_TOTAL 80
// per-layer slot map: Wq:0-1 Wk:2-3 Wv:4-5 Wo:6-7 W1:8-23([nb][kc]) W2:24-39

// GEMM tile: M=64, N=128, Kchunk=64, 4 warps (128 thr), 2 CTAs/SM.
// stage = A-hi 8K + A-lo 8K + B-hi 16K + B-lo 16K = 48KB, double buffered.
#define OA_HI 0u
#define OA_LO 8192u
#define OB_HI 16384u
#define OB_LO 32768u
#define STAGE_B 49152u
#define DSMEM_BYTES (1024 + 2 * STAGE_B)   // 99328

// ---------------------------------------------------------------------------
// Scratch (device globals: the sanctioned no-alloc workaround)
// ---------------------------------------------------------------------------
__device__ float g_X[MTOT * DIM];          // xpe / layer output (fp32)
__device__ float g_Qb[MTOT * DIM];         // q (fp32)
__device__ float g_Kb[MTOT * DIM];         // k, then h (fp32)
__device__ float g_Vb[MTOT * DIM];         // v (fp32)
__device__ float g_Np[BATCH * DIM];
__device__ float g_bnp[2 * 64 * DIM];
__device__ float g_bns[2 * DIM];
__device__ float g_PE[SEQ * DIM];
__device__ __nv_bfloat16 g_Wt[(size_t)SLOTS_TOTAL * SLOT_BF16];
// split-bf16 activation planes (hi plane then lo plane)
__device__ __nv_bfloat16 g_Xs[2 * (size_t)MTOT * DIM];   // QKV input
__device__ __nv_bfloat16 g_Cs[2 * (size_t)MTOT * DIM];   // ctx -> Wo input
__device__ __nv_bfloat16 g_Hs[2 * (size_t)MTOT * DIM];   // h -> FFN1 input
__device__ __nv_bfloat16 g_Fs[2 * (size_t)MTOT * HID];   // ffn hidden -> FFN2 in

__device__ __forceinline__ float* self32(int s) {
    switch (s) {
        case 0: return g_X;
        case 1: return g_Qb;
        case 2: return g_Kb;
        case 3: return g_Vb;
    }
    return nullptr;
}
__device__ __forceinline__ __nv_bfloat16* selbf(int s, size_t& plane) {
    switch (s) {
        case 0: plane = (size_t)MTOT * DIM; return g_Xs;
        case 1: plane = (size_t)MTOT * DIM; return g_Cs;
        case 2: plane = (size_t)MTOT * DIM; return g_Hs;
        case 3: plane = (size_t)MTOT * HID; return g_Fs;
    }
    plane = 0; return nullptr;
}

__device__ __forceinline__ float warp_red(float v) {
    #pragma unroll
    for (int o = 16; o; o >>= 1) v += __shfl_xor_sync(0xffffffffu, v, o);
    return v;
}

// ---------------------------------------------------------------------------
// PTX helpers (family-target-safe: ldmatrix sm_75+, mma/cp.async sm_80+)
// ---------------------------------------------------------------------------
__device__ __forceinline__ uint32_t smem_u32(const void* p) {
    uint32_t a;
    asm("{ .reg .u64 t; cvta.to.shared.u64 t, %1; cvt.u32.u64 %0, t; }"
        : "=r"(a) : "l"(p));
    return a;
}

__device__ __forceinline__ void ldm4(uint32_t* r, uint32_t addr) {
    asm volatile("ldmatrix.sync.aligned.m8n8.x4.shared.b16 {%0,%1,%2,%3}, [%4];"
                 : "=r"(r[0]), "=r"(r[1]), "=r"(r[2]), "=r"(r[3]) : "r"(addr));
}

__device__ __forceinline__ void mma16816(float* c, const uint32_t* a,
                                         const uint32_t* b) {
    asm volatile(
        "mma.sync.aligned.m16n8k16.row.col.f32.bf16.bf16.f32 "
        "{%0,%1,%2,%3}, {%4,%5,%6,%7}, {%8,%9}, {%0,%1,%2,%3};"
        : "+f"(c[0]), "+f"(c[1]), "+f"(c[2]), "+f"(c[3])
        : "r"(a[0]), "r"(a[1]), "r"(a[2]), "r"(a[3]), "r"(b[0]), "r"(b[1]));
}

__device__ __forceinline__ void cpa16(uint32_t dst, const void* src) {
    asm volatile("{ .reg .u64 g; cvta.to.global.u64 g, %1; "
                 "cp.async.cg.shared.global [%0], [g], 16; }"
                 :: "r"(dst), "l"(src));
}
__device__ __forceinline__ void cp_commit() {
    asm volatile("cp.async.commit_group;" ::: "memory");
}
__device__ __forceinline__ void cp_wait0() {
    asm volatile("cp.async.wait_group 0;" ::: "memory");
}
__device__ __forceinline__ void cp_wait1() {
    asm volatile("cp.async.wait_group 1;" ::: "memory");
}

__device__ __forceinline__ uint32_t sw128(uint32_t off) {
    return off ^ ((off >> 3) & 0x70);
}

// split fp32 pair -> packed bf16x2 hi + lo  (RN, identical to __float2bfloat16)
__device__ __forceinline__ uint32_t split_pair(float a, float b, uint32_t& lo) {
    uint32_t h;
    asm("cvt.rn.bf16x2.f32 %0, %1, %2;" : "=r"(h) : "f"(b), "f"(a));
    float ha = __uint_as_float(h << 16);
    float hb = __uint_as_float(h & 0xffff0000u);
    float la = a - ha, lb = b - hb;
    asm("cvt.rn.bf16x2.f32 %0, %1, %2;" : "=r"(lo) : "f"(lb), "f"(la));
    return h;
}

// ---------------------------------------------------------------------------
// PE init + add (also writes split planes for QKV input)
// ---------------------------------------------------------------------------
__global__ void pe_init_kernel() {
    int idx = blockIdx.x * 1024 + threadIdx.x;
    if (idx < SEQ * DIM) {
        int s = idx >> 7, d = idx & 127;
        double e = (double)((d >> 1) * 2) / (double)DIM;
        double p = (double)s / pow(10000.0, e);
        g_PE[idx] = (float)((d & 1) ? cos(p) : sin(p));
    }
}

__global__ void add_pe_kernel(const float* __restrict__ x) {
    size_t i4 = (size_t)blockIdx.x * 256 + threadIdx.x;
    float4 xv = ((const float4*)x)[i4];
    int sd = (int)((i4 * 4) & 2047);
    float4 pv = *(const float4*)(g_PE + sd);
    xv.x += pv.x; xv.y += pv.y; xv.z += pv.z; xv.w += pv.w;
    ((float4*)g_X)[i4] = xv;
    uint32_t l0, l1;
    uint32_t h0 = split_pair(xv.x, xv.y, l0);
    uint32_t h1 = split_pair(xv.z, xv.w, l1);
    const size_t PL = (size_t)MTOT * DIM;
    *(uint2*)(&g_Xs[i4 * 4])      = make_uint2(h0, h1);
    *(uint2*)(&g_Xs[PL + i4 * 4]) = make_uint2(l0, l1);
}

// ---------------------------------------------------------------------------
// Weight prep: transpose + split + swizzle into MMA-ready tiles.
// ---------------------------------------------------------------------------
__global__ __launch_bounds__(256) void prep_weights_kernel(
    const float* __restrict__ Wq, const float* __restrict__ Wk,
    const float* __restrict__ Wv, const float* __restrict__ Wo,
    const float* __restrict__ W1, const float* __restrict__ W2)
{
    int slot = blockIdx.x;
    int l = slot / 40, s = slot % 40;
    const float* W; int Nmat, nb, kc;
    if (s < 8) {
        int m = s >> 1; kc = s & 1; nb = 0; Nmat = 128;
        const float* mats[4] = {Wq, Wk, Wv, Wo};
        W = mats[m] + (size_t)l * DIM * DIM;
    } else if (s < 24) {
        int t = s - 8; nb = t >> 1; kc = t & 1; Nmat = HID;
        W = W1 + (size_t)l * DIM * HID;
    } else {
        int t = s - 24; nb = 0; kc = t; Nmat = 128;
        W = W2 + (size_t)l * HID * DIM;
    }
    char* tile_hi = (char*)(g_Wt + (size_t)slot * SLOT_BF16);
    char* tile_lo = tile_hi + 16384;

    for (int it = 0; it < 4; it++) {
        int g = it * 256 + threadIdx.x;
        int n_local = g >> 3;
        int kq = (g & 7) * 8;
        uint4 hi4, lo4;
        uint32_t* hp = (uint32_t*)&hi4;
        uint32_t* lp = (uint32_t*)&lo4;
        #pragma unroll
        for (int u = 0; u < 4; u++) {
            float v0 = W[(size_t)(kc * 64 + kq + u * 2 + 0) * Nmat + nb * 128 + n_local];
            float v1 = W[(size_t)(kc * 64 + kq + u * 2 + 1) * Nmat + nb * 128 + n_local];
            hp[u] = split_pair(v0, v1, lp[u]);
        }
        uint32_t sw = sw128((uint32_t)(n_local * 128 + kq * 2));
        *(uint4*)(tile_hi + sw) = hi4;
        *(uint4*)(tile_lo + sw) = lo4;
    }
}

// ---------------------------------------------------------------------------
// cp.async double-buffered GEMM core. Tile 64x128, 4 warps.
// warp wn = wid owns cols [wn*32, wn*32+32), all 64 rows.
// 3-product split-bf16: Ahi*Bhi + Ahi*Blo + Alo*Bhi.
// EPI: 0 = bias -> fp32 C; 1 = bias+relu -> split planes; 
//      2 = bias+residual+LN -> fp32 C AND split planes
// ---------------------------------------------------------------------------
template <int EPI>
__device__ __forceinline__ void gemm_cp_core(
    char* dsm_raw,
    const __nv_bfloat16* __restrict__ Ahi, int lda, size_t aplane,
    const __nv_bfloat16* __restrict__ Wslots, int nchunks,
    const float* __restrict__ bias,
    const float* __restrict__ R,
    const float* __restrict__ gam, const float* __restrict__ bet,
    float* __restrict__ C, int ldc,
    __nv_bfloat16* __restrict__ Shi, size_t splane, int lds,
    int ncoloff, int rb)
{
    __shared__ float s_sp[64][4];
    __shared__ float s_sq[64][4];

    uint32_t raw_u = smem_u32(dsm_raw);
    uint32_t sbase = (raw_u + 1023) & ~1023u;

    int tid = threadIdx.x;
    int wn = tid >> 5, lane = tid & 31;

    // ldmatrix lane geometry
    int mt = lane >> 3;
    int rr = lane & 7;
    int row_off = ((mt & 1) << 3) + rr;
    int kk_off = (mt >> 1) << 3;

    float acc[4][4][4];
    #pragma unroll
    for (int i = 0; i < 4; i++)
        #pragma unroll
        for (int j = 0; j < 4; j++)
            #pragma unroll
            for (int r = 0; r < 4; r++) acc[i][j][r] = 0.f;

    // ---- async chunk loader ----
    auto issue = [&](int buf, int c) {
        uint32_t st = sbase + buf * STAGE_B;
        // A planes: 64 rows x 64 k, swizzled dst per 16B granule
        #pragma unroll
        for (int p = 0; p < 4; p++) {
            int g = p * 128 + tid;           // 0..511
            int row = g >> 3, kq = (g & 7) * 8;
            const __nv_bfloat16* srcH =
                Ahi + (size_t)(rb + row) * lda + c * 64 + kq;
            uint32_t sw = sw128((uint32_t)(row * 128 + kq * 2));
            cpa16(st + OA_HI + sw, srcH);
            cpa16(st + OA_LO + sw, srcH + aplane);
        }
        // B: 32KB straight copy (pre-swizzled in global)
        const char* slot = (const char*)(Wslots + (size_t)c * SLOT_BF16);
        #pragma unroll
        for (int p = 0; p < 16; p++) {
            int g = p * 128 + tid;           // 0..2047
            cpa16(st + OB_HI + g * 16, slot + g * 16);
        }
    };

    issue(0, 0);
    cp_commit();

    for (int c = 0; c < nchunks; c++) {
        int buf = c & 1;
        if (c + 1 < nchunks) {
            issue(buf ^ 1, c + 1);
            cp_commit();
            cp_wait1();
        } else {
            cp_wait0();
        }
        __syncthreads();

        uint32_t st = sbase + buf * STAGE_B;
        #pragma unroll
        for (int k16 = 0; k16 < 4; k16++) {
            int kbase = k16 * 16 + kk_off;
            uint32_t bh[4][2], bl[4][2];
            #pragma unroll
            for (int in2 = 0; in2 < 2; in2++) {
                int nrow = wn * 32 + in2 * 16 + row_off;
                uint32_t off = sw128((uint32_t)(nrow * 128 + kbase * 2));
                uint32_t t[4];
                ldm4(t, st + OB_HI + off);
                bh[in2 * 2 + 0][0] = t[0]; bh[in2 * 2 + 0][1] = t[2];
                bh[in2 * 2 + 1][0] = t[1]; bh[in2 * 2 + 1][1] = t[3];
                ldm4(t, st + OB_LO + off);
                bl[in2 * 2 + 0][0] = t[0]; bl[in2 * 2 + 0][1] = t[2];
                bl[in2 * 2 + 1][0] = t[1]; bl[in2 * 2 + 1][1] = t[3];
            }
            uint32_t ah[4][4], al[4][4];
            #pragma unroll
            for (int im = 0; im < 4; im++) {
                int mrow = im * 16 + row_off;
                uint32_t off = sw128((uint32_t)(mrow * 128 + kbase * 2));
                ldm4(ah[im], st + OA_HI + off);
                ldm4(al[im], st + OA_LO + off);
            }
            // product-major sweeps: accumulator reuse distance = 16
            #pragma unroll
            for (int im = 0; im < 4; im++)
                #pragma unroll
                for (int in = 0; in < 4; in++)
                    mma16816(acc[im][in], ah[im], bh[in]);
            #pragma unroll
            for (int im = 0; im < 4; im++)
                #pragma unroll
                for (int in = 0; in < 4; in++)
                    mma16816(acc[im][in], ah[im], bl[in]);
            #pragma unroll
            for (int im = 0; im < 4; im++)
                #pragma unroll
                for (int in = 0; in < 4; in++)
                    mma16816(acc[im][in], al[im], bh[in]);
        }
        __syncthreads();
    }

    // ---- epilogue ----
    int r_in = lane >> 2;
    int c_in = (lane & 3) * 2;

    if (EPI == 0) {
        #pragma unroll
        for (int im = 0; im < 4; im++) {
            size_t gr0 = (size_t)(rb + im * 16 + r_in);
            #pragma unroll
            for (int in = 0; in < 4; in++) {
                int cl = wn * 32 + in * 8 + c_in;
                float b0 = bias[cl], b1 = bias[cl + 1];
                *(float2*)(C + gr0 * ldc + ncoloff + cl) =
                    make_float2(acc[im][in][0] + b0, acc[im][in][1] + b1);
                *(float2*)(C + (gr0 + 8) * ldc + ncoloff + cl) =
                    make_float2(acc[im][in][2] + b0, acc[im][in][3] + b1);
            }
        }
    } else if (EPI == 1) {
        #pragma unroll
        for (int im = 0; im < 4; im++) {
            size_t gr0 = (size_t)(rb + im * 16 + r_in);
            #pragma unroll
            for (int in = 0; in < 4; in++) {
                int cl = wn * 32 + in * 8 + c_in;
                float b0 = bias[cl], b1 = bias[cl + 1];
                float v0 = fmaxf(acc[im][in][0] + b0, 0.f);
                float v1 = fmaxf(acc[im][in][1] + b1, 0.f);
                float v2 = fmaxf(acc[im][in][2] + b0, 0.f);
                float v3 = fmaxf(acc[im][in][3] + b1, 0.f);
                uint32_t lo0, lo1;
                uint32_t h0 = split_pair(v0, v1, lo0);
                uint32_t h1 = split_pair(v2, v3, lo1);
                size_t e0 = gr0 * lds + ncoloff + cl;
                size_t e1 = (gr0 + 8) * lds + ncoloff + cl;
                *(uint32_t*)&Shi[e0] = h0;
                *(uint32_t*)&Shi[splane + e0] = lo0;
                *(uint32_t*)&Shi[e1] = h1;
                *(uint32_t*)&Shi[splane + e1] = lo1;
            }
        }
    } else {
        // pass 1: v = acc + bias + residual; accumulate row partials
        float sv[4][2] = {}, qv[4][2] = {};
        #pragma unroll
        for (int im = 0; im < 4; im++) {
            size_t gr0 = (size_t)(rb + im * 16 + r_in);
            #pragma unroll
            for (int in = 0; in < 4; in++) {
                int cl = wn * 32 + in * 8 + c_in;
                float b0 = bias[cl], b1 = bias[cl + 1];
                float2 rv0 = *(const float2*)(R + gr0 * DIM + cl);
                float2 rv1 = *(const float2*)(R + (gr0 + 8) * DIM + cl);
                float v0 = acc[im][in][0] + b0 + rv0.x;
                float v1 = acc[im][in][1] + b1 + rv0.y;
                float v2 = acc[im][in][2] + b0 + rv1.x;
                float v3 = acc[im][in][3] + b1 + rv1.y;
                acc[im][in][0] = v0; acc[im][in][1] = v1;
                acc[im][in][2] = v2; acc[im][in][3] = v3;
                sv[im][0] += v0 + v1; qv[im][0] += v0 * v0 + v1 * v1;
                sv[im][1] += v2 + v3; qv[im][1] += v2 * v2 + v3 * v3;
            }
        }
        #pragma unroll
        for (int im = 0; im < 4; im++)
            #pragma unroll
            for (int h2 = 0; h2 < 2; h2++) {
                float s = sv[im][h2], q = qv[im][h2];
                s += __shfl_xor_sync(0xffffffffu, s, 1);
                s += __shfl_xor_sync(0xffffffffu, s, 2);
                q += __shfl_xor_sync(0xffffffffu, q, 1);
                q += __shfl_xor_sync(0xffffffffu, q, 2);
                if ((lane & 3) == 0) {
                    int rl = im * 16 + r_in + h2 * 8;
                    s_sp[rl][wn] = s;
                    s_sq[rl][wn] = q;
                }
            }
        __syncthreads();
        float mn[4][2], rs[4][2];
        #pragma unroll
        for (int im = 0; im < 4; im++)
            #pragma unroll
            for (int h2 = 0; h2 < 2; h2++) {
                int rl = im * 16 + r_in + h2 * 8;
                float s = s_sp[rl][0] + s_sp[rl][1] + s_sp[rl][2] + s_sp[rl][3];
                float q = s_sq[rl][0] + s_sq[rl][1] + s_sq[rl][2] + s_sq[rl][3];
                float m = s * (1.f / 128.f);
                float var = q * (1.f / 128.f) - m * m;
                mn[im][h2] = m;
                rs[im][h2] = rsqrtf(var + EPSV);
            }
        #pragma unroll
        for (int im = 0; im < 4; im++) {
            size_t gr0 = (size_t)(rb + im * 16 + r_in);
            #pragma unroll
            for (int in = 0; in < 4; in++) {
                int cl = wn * 32 + in * 8 + c_in;
                float g0 = gam[cl], g1 = gam[cl + 1];
                float e0 = bet[cl], e1 = bet[cl + 1];
                float o0 = (acc[im][in][0] - mn[im][0]) * rs[im][0] * g0 + e0;
                float o1 = (acc[im][in][1] - mn[im][0]) * rs[im][0] * g1 + e1;
                float o2 = (acc[im][in][2] - mn[im][1]) * rs[im][1] * g0 + e0;
                float o3 = (acc[im][in][3] - mn[im][1]) * rs[im][1] * g1 + e1;
                *(float2*)(C + gr0 * ldc + cl) = make_float2(o0, o1);
                *(float2*)(C + (gr0 + 8) * ldc + cl) = make_float2(o2, o3);
                uint32_t lo0, lo1;
                uint32_t h0 = split_pair(o0, o1, lo0);
                uint32_t h1 = split_pair(o2, o3, lo1);
                size_t e0i = gr0 * lds + cl;
                size_t e1i = (gr0 + 8) * lds + cl;
                *(uint32_t*)&Shi[e0i] = h0;
                *(uint32_t*)&Shi[splane + e0i] = lo0;
                *(uint32_t*)&Shi[e1i] = h1;
                *(uint32_t*)&Shi[splane + e1i] = lo1;
            }
        }
    }
}

// Generic GEMM kernel: blockIdx.x = col block, blockIdx.y = row block (64)
template <int EPI>
__global__ __launch_bounds__(128, 2) void gemm_cp_kernel(
    int absel, int lda, int slotbase, int kchunks,
    const float* __restrict__ bias, int rsel,
    const float* __restrict__ gam, const float* __restrict__ bet,
    int csel, int ldc, int ssel, int lds)
{
    extern __shared__ char dsm[];
    int nb = blockIdx.x;
    int rb = blockIdx.y * 64;
    size_t aplane, splane = 0;
    const __nv_bfloat16* Ahi = selbf(absel, aplane);
    __nv_bfloat16* Shi = (ssel >= 0) ? selbf(ssel, splane) : nullptr;
    const __nv_bfloat16* Ws =
        g_Wt + ((size_t)slotbase + (size_t)nb * kchunks) * SLOT_BF16;
    gemm_cp_core<EPI>(dsm, Ahi, lda, aplane, Ws, kchunks,
                      bias + nb * 128,
                      rsel >= 0 ? self32(rsel) : nullptr, gam, bet,
                      csel >= 0 ? self32(csel) : nullptr, ldc,
                      Shi, splane, lds, nb * 128, rb);
}

// QKV fused: blockIdx.x selects q/k/v (co-scheduled -> A L2 reuse)
__global__ __launch_bounds__(128, 2) void qkv_cp_kernel(
    int lslot, const float* __restrict__ bq,
    const float* __restrict__ bk, const float* __restrict__ bv)
{
    extern __shared__ char dsm[];
    int which = blockIdx.x;
    int rb = blockIdx.y * 64;
    const __nv_bfloat16* Ws = g_Wt + (size_t)(lslot + which * 2) * SLOT_BF16;
    const float* bias = (which == 0) ? bq : (which == 1) ? bk : bv;
    float* C = (which == 0) ? g_Qb : (which == 1) ? g_Kb : g_Vb;
    gemm_cp_core<0>(dsm, g_Xs, DIM, (size_t)MTOT * DIM, Ws, 2, bias,
                    nullptr, nullptr, nullptr, C, DIM,
                    nullptr, 0, 0, 0, rb);
}

// ---------------------------------------------------------------------------
// Attention: one warp per 16x16 unit; writes ctx as split planes (g_Cs)
// ---------------------------------------------------------------------------
__global__ __launch_bounds__(256) void attn_kernel() {
    __shared__ float s_q[8][256];
    __shared__ float s_k[8][256];
    __shared__ float s_v[8][256];

    int w = threadIdx.x >> 5, lane = threadIdx.x & 31;
    size_t n = (size_t)blockIdx.x * 8 + w;
    size_t bse = n * 256;

    const float4* q4 = (const float4*)(g_Qb + bse);
    const float4* k4 = (const float4*)(g_Kb + bse);
    const float4* v4 = (const float4*)(g_Vb + bse);
    ((float4*)s_q[w])[lane]      = q4[lane];
    ((float4*)s_q[w])[lane + 32] = q4[lane + 32];
    ((float4*)s_k[w])[lane]      = k4[lane];
    ((float4*)s_k[w])[lane + 32] = k4[lane + 32];
    ((float4*)s_v[w])[lane]      = v4[lane];
    ((float4*)s_v[w])[lane + 32] = v4[lane + 32];
    __syncwarp();

    int i = lane >> 1;
    int jb = (lane & 1) * 8;

    float qr[16];
    #pragma unroll
    for (int u = 0; u < 4; u++) {
        float4 t4 = *(const float4*)&s_q[w][i * 16 + u * 4];
        qr[u * 4 + 0] = t4.x; qr[u * 4 + 1] = t4.y;
        qr[u * 4 + 2] = t4.z; qr[u * 4 + 3] = t4.w;
    }

    float sc[8];
    #pragma unroll
    for (int j = 0; j < 8; j++) {
        const float* kr = &s_k[w][(jb + j) * 16];
        float dd = 0.f;
        #pragma unroll
        for (int u = 0; u < 16; u++) dd = fmaf(qr[u], kr[u], dd);
        sc[j] = dd * 0.25f;
    }

    float mx = sc[0];
    #pragma unroll
    for (int j = 1; j < 8; j++) mx = fmaxf(mx, sc[j]);
    mx = fmaxf(mx, __shfl_xor_sync(0xffffffffu, mx, 1));

    float sum = 0.f;
    #pragma unroll
    for (int j = 0; j < 8; j++) { sc[j] = __expf(sc[j] - mx); sum += sc[j]; }
    sum += __shfl_xor_sync(0xffffffffu, sum, 1);
    float inv = 1.f / sum;

    float acc[16] = {};
    #pragma unroll
    for (int j = 0; j < 8; j++) {
        float p = sc[j] * inv;
        const float* vr = &s_v[w][(jb + j) * 16];
        #pragma unroll
        for (int u = 0; u < 16; u++) acc[u] = fmaf(p, vr[u], acc[u]);
    }
    #pragma unroll
    for (int u = 0; u < 16; u++)
        acc[u] += __shfl_xor_sync(0xffffffffu, acc[u], 1);

    int db = (lane & 1) * 8;
    uint32_t hw[4], lw[4];
    #pragma unroll
    for (int u2 = 0; u2 < 4; u2++)
        hw[u2] = split_pair(acc[db + u2 * 2], acc[db + u2 * 2 + 1], lw[u2]);
    const size_t PL = (size_t)MTOT * DIM;
    size_t e = bse + i * 16 + db;
    *(uint4*)(&g_Cs[e])      = make_uint4(hw[0], hw[1], hw[2], hw[3]);
    *(uint4*)(&g_Cs[PL + e]) = make_uint4(lw[0], lw[1], lw[2], lw[3]);
}

// ---------------------------------------------------------------------------
// Head
// ---------------------------------------------------------------------------
__global__ __launch_bounds__(128) void numproj_kernel(
    const float* __restrict__ num, const float* __restrict__ Wn,
    const float* __restrict__ bnum)
{
    __shared__ float sn[NUMF];
    int b = blockIdx.x, t = threadIdx.x;
    if (t < NUMF) sn[t] = num[(size_t)b * NUMF + t];
    __syncthreads();
    float acc = bnum[t];
    #pragma unroll 1
    for (int k = 0; k < NUMF; k++)
        acc = fmaf(sn[k], Wn[k * DIM + t], acc);
    g_Np[(size_t)b * DIM + t] = acc;
}

__global__ __launch_bounds__(256) void bn_partial_kernel() {
    int j = blockIdx.x, t = threadIdx.x;
    int col = t & 127, half = t >> 7;
    float s = 0.f, q = 0.f;
    for (int i = 0; i < 64; i++) {
        float v = g_Np[(size_t)(j * 128 + half * 64 + i) * DIM + col];
        s += v; q += v * v;
    }
    __shared__ float ss[256], sq[256];
    ss[t] = s; sq[t] = q;
    __syncthreads();
    if (half == 0) {
        g_bnp[j * DIM + col]            = ss[t] + ss[t + 128];
        g_bnp[64 * DIM + j * DIM + col] = sq[t] + sq[t + 128];
    }
}

__global__ __launch_bounds__(128) void bn_final_kernel(
    const float* __restrict__ gamma, const float* __restrict__ beta)
{
    int c = threadIdx.x;
    float s = 0.f, q = 0.f;
    for (int j = 0; j < 64; j++) {
        s += g_bnp[j * DIM + c];
        q += g_bnp[64 * DIM + j * DIM + c];
    }
    float mu = s * (1.f / 8192.f);
    float var = q * (1.f / 8192.f) - mu * mu;
    float a = gamma[c] * rsqrtf(var + EPSV);
    g_bns[c] = a;
    g_bns[DIM + c] = beta[c] - mu * a;
}

__global__ __launch_bounds__(256) void final_kernel(
    const float* __restrict__ gcn, const float* __restrict__ Wf,
    const float* __restrict__ bf, float* __restrict__ out)
{
    int b = blockIdx.x, t = threadIdx.x;
    const float* xr = g_X + (size_t)b * (SEQ * DIM);
    float acc = 0.f;
    #pragma unroll
    for (int i = 0; i < 8; i++) {
        int idx = t + 256 * i;
        acc = fmaf(xr[idx], Wf[idx], acc);
    }
    if (t < GCN)
        acc = fmaf(gcn[(size_t)b * GCN + t], Wf[SEQ * DIM + t], acc);
    if (t < DIM) {
        float v = g_Np[(size_t)b * DIM + t] * g_bns[t] + g_bns[DIM + t];
        acc = fmaf(v, Wf[SEQ * DIM + GCN + t], acc);
    }
    acc = warp_red(acc);
    __shared__ float red[8];
    if ((t & 31) == 0) red[t >> 5] = acc;
    __syncthreads();
    if (t == 0) {
        float z = red[0] + red[1] + red[2] + red[3]
                + red[4] + red[5] + red[6] + red[7] + bf[0];
        out[b] = 1.f / (1.f + expf(-z));
    }
}

// ---------------------------------------------------------------------------
// Launch
// ---------------------------------------------------------------------------
extern "C" void kernel_launch(void* const* d_in, const int* in_sizes, int n_in,
                              void* d_out, int out_size)
{
    const float* x    = (const float*)d_in[0];
    const float* gcn  = (const float*)d_in[1];
    const float* num  = (const float*)d_in[2];
    const float* Wq   = (const float*)d_in[3];
    const float* bq   = (const float*)d_in[4];
    const float* Wk   = (const float*)d_in[5];
    const float* bk   = (const float*)d_in[6];
    const float* Wv   = (const float*)d_in[7];
    const float* bv   = (const float*)d_in[8];
    const float* Wo   = (const float*)d_in[9];
    const float* bo   = (const float*)d_in[10];
    const float* ln1g = (const float*)d_in[11];
    const float* ln1b = (const float*)d_in[12];
    const float* W1   = (const float*)d_in[13];
    const float* b1   = (const float*)d_in[14];
    const float* W2   = (const float*)d_in[15];
    const float* b2   = (const float*)d_in[16];
    const float* ln2g = (const float*)d_in[17];
    const float* ln2b = (const float*)d_in[18];
    const float* Wn   = (const float*)d_in[19];
    const float* bnum = (const float*)d_in[20];
    const float* bng  = (const float*)d_in[21];
    const float* bnb  = (const float*)d_in[22];
    const float* Wf   = (const float*)d_in[23];
    const float* bf   = (const float*)d_in[24];
    float* out = (float*)d_out;

    cudaFuncSetAttribute(qkv_cp_kernel,
        cudaFuncAttributeMaxDynamicSharedMemorySize, DSMEM_BYTES);
    cudaFuncSetAttribute(gemm_cp_kernel<1>,
        cudaFuncAttributeMaxDynamicSharedMemorySize, DSMEM_BYTES);
    cudaFuncSetAttribute(gemm_cp_kernel<2>,
        cudaFuncAttributeMaxDynamicSharedMemorySize, DSMEM_BYTES);

    pe_init_kernel<<<2, 1024>>>();
    prep_weights_kernel<<<SLOTS_TOTAL, 256>>>(Wq, Wk, Wv, Wo, W1, W2);
    add_pe_kernel<<<16384, 256>>>(x);

    const int RB = MTOT / 64;   // 2048 row blocks
    for (int l = 0; l < 2; l++) {
        int lb = l * 40;
        // QKV: g_Xs -> Q,K,V (fp32)
        qkv_cp_kernel<<<dim3(3, RB), 128, DSMEM_BYTES>>>(
            lb, bq + l * DIM, bk + l * DIM, bv + l * DIM);
        // attention: fp32 q,k,v -> ctx split planes (g_Cs)
        attn_kernel<<<MTOT / 16, 256>>>();
        // h = LN(ctx @ Wo + bo + X): fp32 -> g_Kb, split -> g_Hs
        gemm_cp_kernel<2><<<dim3(1, RB), 128, DSMEM_BYTES>>>(
            1, DIM, lb + 6, 2, bo + l * DIM, 0,
            ln1g + l * DIM, ln1b + l * DIM, 2, DIM, 2, DIM);
        // ffn hidden = relu(h @ W1 + b1): split -> g_Fs
        gemm_cp_kernel<1><<<dim3(8, RB), 128, DSMEM_BYTES>>>(
            2, DIM, lb + 8, 2, b1 + l * HID, -1,
            nullptr, nullptr, -1, 0, 3, HID);
        // out = LN(ffn @ W2 + b2 + h): fp32 -> g_X, split -> g_Xs
        gemm_cp_kernel<2><<<dim3(1, RB), 128, DSMEM_BYTES>>>(
            3, HID, lb + 24, 16, b2 + l * DIM, 2,
            ln2g + l * DIM, ln2b + l * DIM, 0, DIM, 0, DIM);
    }

    numproj_kernel<<<BATCH, 128>>>(num, Wn, bnum);
    bn_partial_kernel<<<64, 256>>>();
    bn_final_kernel<<<1, 128>>>(bng, bnb);
    final_kernel<<<BATCH, 256>>>(gcn, Wf, bf, out);
}

// round 9
// speedup vs baseline: 2.3232x; 1.0075x over previous
#include <cuda_runtime.h>
#include <cuda_bf16.h>
#include <math.h>
#include <stdint.h>

// ---------------------------------------------------------------------------
// Problem constants
// ---------------------------------------------------------------------------
#define BATCH 8192
#define SEQ   16
#define DIM   128
#define MTOT  (BATCH * SEQ)        // 131072 rows
#define HID   1024
#define GCN   40
#define NUMF  103
#define EPSV  1e-5f

// Weight-tile store: each "slot" = one 128(N)x32(K) tile, hi then lo bf16,
// SW64-swizzled 64B rows — ldmatrix-ready. 4096 bf16 per plane.
#define SLOT_BF16   8192             // hi(4096) + lo(4096) = 16KB
#define SLOTS_TOTAL 160              // 80 per layer x 2 layers
// per-layer map: Wq:0-3 Wk:4-7 Wv:8-11 Wo:12-15 W1:16+nb*4+kc W2:48+kc

// GEMM tile: M=128, N=128, Kchunk=32, 8 warps (256 thr), 2 CTAs/SM.
// stage = A-hi 8K + A-lo 8K + B-hi 8K + B-lo 8K = 32KB, 3-stage ring.
#define KCH   32
#define OA_HI 0u
#define OA_LO 8192u
#define OB_HI 16384u
#define STAGE_B 32768u
#define NSTAGE 3
#define DSMEM_BYTES (1024 + NSTAGE * STAGE_B)   // 99328

// ---------------------------------------------------------------------------
// Scratch (device globals: the sanctioned no-alloc workaround)
// ---------------------------------------------------------------------------
__device__ float g_X[MTOT * DIM];          // xpe / layer output (fp32)
__device__ float g_Qb[MTOT * DIM];         // q (fp32)
__device__ float g_Kb[MTOT * DIM];         // k, then h (fp32)
__device__ float g_Vb[MTOT * DIM];         // v (fp32)
__device__ float g_Np[BATCH * DIM];
__device__ float g_bnp[2 * 64 * DIM];
__device__ float g_bns[2 * DIM];
__device__ float g_PE[SEQ * DIM];
__device__ __nv_bfloat16 g_Wt[(size_t)SLOTS_TOTAL * SLOT_BF16];
// split-bf16 activation planes (hi plane then lo plane)
__device__ __nv_bfloat16 g_Xs[2 * (size_t)MTOT * DIM];   // QKV input
__device__ __nv_bfloat16 g_Cs[2 * (size_t)MTOT * DIM];   // ctx -> Wo input
__device__ __nv_bfloat16 g_Hs[2 * (size_t)MTOT * DIM];   // h -> FFN1 input
__device__ __nv_bfloat16 g_Fs[2 * (size_t)MTOT * HID];   // ffn hidden -> FFN2 in

__device__ __forceinline__ float* self32(int s) {
    switch (s) {
        case 0: return g_X;
        case 1: return g_Qb;
        case 2: return g_Kb;
        case 3: return g_Vb;
    }
    return nullptr;
}
__device__ __forceinline__ __nv_bfloat16* selbf(int s, size_t& plane) {
    switch (s) {
        case 0: plane = (size_t)MTOT * DIM; return g_Xs;
        case 1: plane = (size_t)MTOT * DIM; return g_Cs;
        case 2: plane = (size_t)MTOT * DIM; return g_Hs;
        case 3: plane = (size_t)MTOT * HID; return g_Fs;
    }
    plane = 0; return nullptr;
}

__device__ __forceinline__ float warp_red(float v) {
    #pragma unroll
    for (int o = 16; o; o >>= 1) v += __shfl_xor_sync(0xffffffffu, v, o);
    return v;
}

// ---------------------------------------------------------------------------
// PTX helpers (family-target-safe: ldmatrix sm_75+, mma/cp.async sm_80+)
// ---------------------------------------------------------------------------
__device__ __forceinline__ uint32_t smem_u32(const void* p) {
    uint32_t a;
    asm("{ .reg .u64 t; cvta.to.shared.u64 t, %1; cvt.u32.u64 %0, t; }"
        : "=r"(a) : "l"(p));
    return a;
}

__device__ __forceinline__ void ldm4(uint32_t* r, uint32_t addr) {
    asm volatile("ldmatrix.sync.aligned.m8n8.x4.shared.b16 {%0,%1,%2,%3}, [%4];"
                 : "=r"(r[0]), "=r"(r[1]), "=r"(r[2]), "=r"(r[3]) : "r"(addr));
}

__device__ __forceinline__ void mma16816(float* c, const uint32_t* a,
                                         const uint32_t* b) {
    asm volatile(
        "mma.sync.aligned.m16n8k16.row.col.f32.bf16.bf16.f32 "
        "{%0,%1,%2,%3}, {%4,%5,%6,%7}, {%8,%9}, {%0,%1,%2,%3};"
        : "+f"(c[0]), "+f"(c[1]), "+f"(c[2]), "+f"(c[3])
        : "r"(a[0]), "r"(a[1]), "r"(a[2]), "r"(a[3]), "r"(b[0]), "r"(b[1]));
}

__device__ __forceinline__ void cpa16(uint32_t dst, const void* src) {
    asm volatile("{ .reg .u64 g; cvta.to.global.u64 g, %1; "
                 "cp.async.cg.shared.global [%0], [g], 16; }"
                 :: "r"(dst), "l"(src));
}
__device__ __forceinline__ void cp_commit() {
    asm volatile("cp.async.commit_group;" ::: "memory");
}
__device__ __forceinline__ void cp_wait0() {
    asm volatile("cp.async.wait_group 0;" ::: "memory");
}
__device__ __forceinline__ void cp_wait1() {
    asm volatile("cp.async.wait_group 1;" ::: "memory");
}

// SW64 swizzle for 64-byte rows: granule column ^= (row>>1)&3 — conflict-free
// for ldmatrix 8-row phases.
__device__ __forceinline__ uint32_t sw64(uint32_t off) {
    return off ^ ((off >> 3) & 0x30);
}

// split fp32 pair -> packed bf16x2 hi + lo  (RN, identical to __float2bfloat16)
__device__ __forceinline__ uint32_t split_pair(float a, float b, uint32_t& lo) {
    uint32_t h;
    asm("cvt.rn.bf16x2.f32 %0, %1, %2;" : "=r"(h) : "f"(b), "f"(a));
    float ha = __uint_as_float(h << 16);
    float hb = __uint_as_float(h & 0xffff0000u);
    float la = a - ha, lb = b - hb;
    asm("cvt.rn.bf16x2.f32 %0, %1, %2;" : "=r"(lo) : "f"(lb), "f"(la));
    return h;
}

// ---------------------------------------------------------------------------
// PE init + add (also writes split planes for QKV input)
// ---------------------------------------------------------------------------
__global__ void pe_init_kernel() {
    int idx = blockIdx.x * 1024 + threadIdx.x;
    if (idx < SEQ * DIM) {
        int s = idx >> 7, d = idx & 127;
        double e = (double)((d >> 1) * 2) / (double)DIM;
        double p = (double)s / pow(10000.0, e);
        g_PE[idx] = (float)((d & 1) ? cos(p) : sin(p));
    }
}

__global__ void add_pe_kernel(const float* __restrict__ x) {
    size_t i4 = (size_t)blockIdx.x * 256 + threadIdx.x;
    float4 xv = ((const float4*)x)[i4];
    int sd = (int)((i4 * 4) & 2047);
    float4 pv = *(const float4*)(g_PE + sd);
    xv.x += pv.x; xv.y += pv.y; xv.z += pv.z; xv.w += pv.w;
    ((float4*)g_X)[i4] = xv;
    uint32_t l0, l1;
    uint32_t h0 = split_pair(xv.x, xv.y, l0);
    uint32_t h1 = split_pair(xv.z, xv.w, l1);
    const size_t PL = (size_t)MTOT * DIM;
    *(uint2*)(&g_Xs[i4 * 4])      = make_uint2(h0, h1);
    *(uint2*)(&g_Xs[PL + i4 * 4]) = make_uint2(l0, l1);
}

// ---------------------------------------------------------------------------
// Weight prep: transpose + split + SW64-swizzle into 128x32 MMA-ready tiles.
// ---------------------------------------------------------------------------
__global__ __launch_bounds__(256) void prep_weights_kernel(
    const float* __restrict__ Wq, const float* __restrict__ Wk,
    const float* __restrict__ Wv, const float* __restrict__ Wo,
    const float* __restrict__ W1, const float* __restrict__ W2)
{
    int slot = blockIdx.x;
    int l = slot / 80, s = slot % 80;
    const float* W; int Nmat, nb, kc;
    if (s < 16) {
        int m = s >> 2; kc = s & 3; nb = 0; Nmat = 128;
        const float* mats[4] = {Wq, Wk, Wv, Wo};
        W = mats[m] + (size_t)l * DIM * DIM;
    } else if (s < 48) {
        int t = s - 16; nb = t >> 2; kc = t & 3; Nmat = HID;
        W = W1 + (size_t)l * DIM * HID;
    } else {
        int t = s - 48; nb = 0; kc = t; Nmat = 128;
        W = W2 + (size_t)l * HID * DIM;
    }
    char* tile_hi = (char*)(g_Wt + (size_t)slot * SLOT_BF16);
    char* tile_lo = tile_hi + 8192;

    #pragma unroll
    for (int it = 0; it < 2; it++) {
        int g = it * 256 + threadIdx.x;    // 16B granule 0..511
        int n_local = g >> 2;
        int kq = (g & 3) * 8;
        uint4 hi4, lo4;
        uint32_t* hp = (uint32_t*)&hi4;
        uint32_t* lp = (uint32_t*)&lo4;
        #pragma unroll
        for (int u = 0; u < 4; u++) {
            float v0 = W[(size_t)(kc * 32 + kq + u * 2 + 0) * Nmat + nb * 128 + n_local];
            float v1 = W[(size_t)(kc * 32 + kq + u * 2 + 1) * Nmat + nb * 128 + n_local];
            hp[u] = split_pair(v0, v1, lp[u]);
        }
        uint32_t sw = sw64((uint32_t)(n_local * 64 + kq * 2));
        *(uint4*)(tile_hi + sw) = hi4;
        *(uint4*)(tile_lo + sw) = lo4;
    }
}

// ---------------------------------------------------------------------------
// cp.async 3-stage GEMM core. Tile 128x128, 8 warps, Kchunk=32.
// warp: wm = wid&1 -> rows wm*64+[0,64); wn = wid>>1 -> cols wn*32+[0,32).
// 3-product split-bf16: Ahi*Bhi + Ahi*Blo + Alo*Bhi.
// EPI: 0 = bias -> fp32 C; 1 = bias+relu -> split planes;
//      2 = bias+residual+LN -> fp32 C AND split planes
// ---------------------------------------------------------------------------
template <int EPI>
__device__ __forceinline__ void gemm_cp_core(
    char* dsm_raw,
    const __nv_bfloat16* __restrict__ Ahi, int lda, size_t aplane,
    const __nv_bfloat16* __restrict__ Wslots, int nchunks,
    const float* __restrict__ bias,
    const float* __restrict__ R,
    const float* __restrict__ gam, const float* __restrict__ bet,
    float* __restrict__ C, int ldc,
    __nv_bfloat16* __restrict__ Shi, size_t splane, int lds,
    int ncoloff, int rb)
{
    __shared__ float s_sp[128][4];
    __shared__ float s_sq[128][4];

    uint32_t raw_u = smem_u32(dsm_raw);
    uint32_t sbase = (raw_u + 1023) & ~1023u;

    int tid = threadIdx.x;
    int wid = tid >> 5, lane = tid & 31;
    int wm = wid & 1, wn = wid >> 1;

    // ldmatrix lane geometry
    int mt = lane >> 3;
    int rr = lane & 7;
    int row_off = ((mt & 1) << 3) + rr;
    int kk_off = (mt >> 1) << 3;

    // hoisted per-thread loader geometry (2 A granules, 4 B granules)
    uint32_t ag_sw[2];
    const __nv_bfloat16* ag_src[2];
    #pragma unroll
    for (int p = 0; p < 2; p++) {
        int g = p * 256 + tid;             // 0..511
        int arow = g >> 2, kq = (g & 3) * 8;
        ag_sw[p] = sw64((uint32_t)(arow * 64 + kq * 2));
        ag_src[p] = Ahi + (size_t)(rb + arow) * lda + kq;
    }
    const char* bbase = (const char*)Wslots;

    float acc[4][4][4];
    #pragma unroll
    for (int i = 0; i < 4; i++)
        #pragma unroll
        for (int j = 0; j < 4; j++)
            #pragma unroll
            for (int r = 0; r < 4; r++) acc[i][j][r] = 0.f;

    auto issue = [&](int buf, int c) {
        uint32_t st = sbase + buf * STAGE_B;
        #pragma unroll
        for (int p = 0; p < 2; p++) {
            const __nv_bfloat16* srcH = ag_src[p] + c * KCH;
            cpa16(st + OA_HI + ag_sw[p], srcH);
            cpa16(st + OA_LO + ag_sw[p], srcH + aplane);
        }
        // B slot: 16KB straight copy (hi 8KB then lo 8KB, pre-swizzled)
        const char* bs = bbase + (size_t)c * (SLOT_BF16 * 2);
        #pragma unroll
        for (int p = 0; p < 4; p++) {
            uint32_t off = (uint32_t)((p * 256 + tid) * 16);
            cpa16(st + OB_HI + off, bs + off);
        }
    };

    issue(0, 0);
    cp_commit();
    if (nchunks > 1) { issue(1, 1); cp_commit(); }

    for (int c = 0; c < nchunks; c++) {
        if (c + 1 < nchunks) cp_wait1(); else cp_wait0();
        __syncthreads();
        if (c + 2 < nchunks) { issue((c + 2) % NSTAGE, c + 2); cp_commit(); }

        uint32_t st = sbase + (c % NSTAGE) * STAGE_B;
        #pragma unroll
        for (int k16 = 0; k16 < 2; k16++) {
            int kbase = k16 * 16 + kk_off;
            // B fragments
            uint32_t bh[4][2], bl[4][2];
            #pragma unroll
            for (int in2 = 0; in2 < 2; in2++) {
                int nrow = wn * 32 + in2 * 16 + row_off;
                uint32_t off = sw64((uint32_t)(nrow * 64 + kbase * 2));
                uint32_t t[4];
                ldm4(t, st + OB_HI + off);
                bh[in2 * 2 + 0][0] = t[0]; bh[in2 * 2 + 0][1] = t[2];
                bh[in2 * 2 + 1][0] = t[1]; bh[in2 * 2 + 1][1] = t[3];
                ldm4(t, st + OB_HI + 8192u + off);
                bl[in2 * 2 + 0][0] = t[0]; bl[in2 * 2 + 0][1] = t[2];
                bl[in2 * 2 + 1][0] = t[1]; bl[in2 * 2 + 1][1] = t[3];
            }
            // A-hi fragments, then hh + hl sweeps
            uint32_t ah[4][4];
            #pragma unroll
            for (int im = 0; im < 4; im++) {
                int mrow = wm * 64 + im * 16 + row_off;
                ldm4(ah[im], st + OA_HI + sw64((uint32_t)(mrow * 64 + kbase * 2)));
            }
            #pragma unroll
            for (int im = 0; im < 4; im++)
                #pragma unroll
                for (int in = 0; in < 4; in++)
                    mma16816(acc[im][in], ah[im], bh[in]);
            #pragma unroll
            for (int im = 0; im < 4; im++)
                #pragma unroll
                for (int in = 0; in < 4; in++)
                    mma16816(acc[im][in], ah[im], bl[in]);
            // A-lo fragments, lh sweep
            uint32_t al[4][4];
            #pragma unroll
            for (int im = 0; im < 4; im++) {
                int mrow = wm * 64 + im * 16 + row_off;
                ldm4(al[im], st + OA_LO + sw64((uint32_t)(mrow * 64 + kbase * 2)));
            }
            #pragma unroll
            for (int im = 0; im < 4; im++)
                #pragma unroll
                for (int in = 0; in < 4; in++)
                    mma16816(acc[im][in], al[im], bh[in]);
        }
        __syncthreads();
    }

    // ---- epilogue ----
    int r_in = lane >> 2;
    int c_in = (lane & 3) * 2;

    if (EPI == 0) {
        #pragma unroll
        for (int im = 0; im < 4; im++) {
            size_t gr0 = (size_t)(rb + wm * 64 + im * 16 + r_in);
            #pragma unroll
            for (int in = 0; in < 4; in++) {
                int cl = wn * 32 + in * 8 + c_in;
                float b0 = bias[cl], b1 = bias[cl + 1];
                *(float2*)(C + gr0 * ldc + ncoloff + cl) =
                    make_float2(acc[im][in][0] + b0, acc[im][in][1] + b1);
                *(float2*)(C + (gr0 + 8) * ldc + ncoloff + cl) =
                    make_float2(acc[im][in][2] + b0, acc[im][in][3] + b1);
            }
        }
    } else if (EPI == 1) {
        #pragma unroll
        for (int im = 0; im < 4; im++) {
            size_t gr0 = (size_t)(rb + wm * 64 + im * 16 + r_in);
            #pragma unroll
            for (int in = 0; in < 4; in++) {
                int cl = wn * 32 + in * 8 + c_in;
                float b0 = bias[cl], b1 = bias[cl + 1];
                float v0 = fmaxf(acc[im][in][0] + b0, 0.f);
                float v1 = fmaxf(acc[im][in][1] + b1, 0.f);
                float v2 = fmaxf(acc[im][in][2] + b0, 0.f);
                float v3 = fmaxf(acc[im][in][3] + b1, 0.f);
                uint32_t lo0, lo1;
                uint32_t h0 = split_pair(v0, v1, lo0);
                uint32_t h1 = split_pair(v2, v3, lo1);
                size_t e0 = gr0 * lds + ncoloff + cl;
                size_t e1 = (gr0 + 8) * lds + ncoloff + cl;
                *(uint32_t*)&Shi[e0] = h0;
                *(uint32_t*)&Shi[splane + e0] = lo0;
                *(uint32_t*)&Shi[e1] = h1;
                *(uint32_t*)&Shi[splane + e1] = lo1;
            }
        }
    } else {
        float sv[4][2] = {}, qv[4][2] = {};
        #pragma unroll
        for (int im = 0; im < 4; im++) {
            size_t gr0 = (size_t)(rb + wm * 64 + im * 16 + r_in);
            #pragma unroll
            for (int in = 0; in < 4; in++) {
                int cl = wn * 32 + in * 8 + c_in;
                float b0 = bias[cl], b1 = bias[cl + 1];
                float2 rv0 = *(const float2*)(R + gr0 * DIM + cl);
                float2 rv1 = *(const float2*)(R + (gr0 + 8) * DIM + cl);
                float v0 = acc[im][in][0] + b0 + rv0.x;
                float v1 = acc[im][in][1] + b1 + rv0.y;
                float v2 = acc[im][in][2] + b0 + rv1.x;
                float v3 = acc[im][in][3] + b1 + rv1.y;
                acc[im][in][0] = v0; acc[im][in][1] = v1;
                acc[im][in][2] = v2; acc[im][in][3] = v3;
                sv[im][0] += v0 + v1; qv[im][0] += v0 * v0 + v1 * v1;
                sv[im][1] += v2 + v3; qv[im][1] += v2 * v2 + v3 * v3;
            }
        }
        #pragma unroll
        for (int im = 0; im < 4; im++)
            #pragma unroll
            for (int h2 = 0; h2 < 2; h2++) {
                float s = sv[im][h2], q = qv[im][h2];
                s += __shfl_xor_sync(0xffffffffu, s, 1);
                s += __shfl_xor_sync(0xffffffffu, s, 2);
                q += __shfl_xor_sync(0xffffffffu, q, 1);
                q += __shfl_xor_sync(0xffffffffu, q, 2);
                if ((lane & 3) == 0) {
                    int rl = wm * 64 + im * 16 + r_in + h2 * 8;
                    s_sp[rl][wn] = s;
                    s_sq[rl][wn] = q;
                }
            }
        __syncthreads();
        float mn[4][2], rs[4][2];
        #pragma unroll
        for (int im = 0; im < 4; im++)
            #pragma unroll
            for (int h2 = 0; h2 < 2; h2++) {
                int rl = wm * 64 + im * 16 + r_in + h2 * 8;
                float s = s_sp[rl][0] + s_sp[rl][1] + s_sp[rl][2] + s_sp[rl][3];
                float q = s_sq[rl][0] + s_sq[rl][1] + s_sq[rl][2] + s_sq[rl][3];
                float m = s * (1.f / 128.f);
                float var = q * (1.f / 128.f) - m * m;
                mn[im][h2] = m;
                rs[im][h2] = rsqrtf(var + EPSV);
            }
        #pragma unroll
        for (int im = 0; im < 4; im++) {
            size_t gr0 = (size_t)(rb + wm * 64 + im * 16 + r_in);
            #pragma unroll
            for (int in = 0; in < 4; in++) {
                int cl = wn * 32 + in * 8 + c_in;
                float g0 = gam[cl], g1 = gam[cl + 1];
                float e0 = bet[cl], e1 = bet[cl + 1];
                float o0 = (acc[im][in][0] - mn[im][0]) * rs[im][0] * g0 + e0;
                float o1 = (acc[im][in][1] - mn[im][0]) * rs[im][0] * g1 + e1;
                float o2 = (acc[im][in][2] - mn[im][1]) * rs[im][1] * g0 + e0;
                float o3 = (acc[im][in][3] - mn[im][1]) * rs[im][1] * g1 + e1;
                *(float2*)(C + gr0 * ldc + cl) = make_float2(o0, o1);
                *(float2*)(C + (gr0 + 8) * ldc + cl) = make_float2(o2, o3);
                uint32_t lo0, lo1;
                uint32_t h0 = split_pair(o0, o1, lo0);
                uint32_t h1 = split_pair(o2, o3, lo1);
                size_t e0i = gr0 * lds + cl;
                size_t e1i = (gr0 + 8) * lds + cl;
                *(uint32_t*)&Shi[e0i] = h0;
                *(uint32_t*)&Shi[splane + e0i] = lo0;
                *(uint32_t*)&Shi[e1i] = h1;
                *(uint32_t*)&Shi[splane + e1i] = lo1;
            }
        }
    }
}

// Generic GEMM kernel: blockIdx.x = col block, blockIdx.y = row block (128)
template <int EPI>
__global__ __launch_bounds__(256, 2) void gemm_cp_kernel(
    int absel, int lda, int slotbase, int kchunks,
    const float* __restrict__ bias, int rsel,
    const float* __restrict__ gam, const float* __restrict__ bet,
    int csel, int ldc, int ssel, int lds)
{
    extern __shared__ char dsm[];
    int nb = blockIdx.x;
    int rb = blockIdx.y * 128;
    size_t aplane, splane = 0;
    const __nv_bfloat16* Ahi = selbf(absel, aplane);
    __nv_bfloat16* Shi = (ssel >= 0) ? selbf(ssel, splane) : nullptr;
    const __nv_bfloat16* Ws =
        g_Wt + ((size_t)slotbase + (size_t)nb * kchunks) * SLOT_BF16;
    gemm_cp_core<EPI>(dsm, Ahi, lda, aplane, Ws, kchunks,
                      bias + nb * 128,
                      rsel >= 0 ? self32(rsel) : nullptr, gam, bet,
                      csel >= 0 ? self32(csel) : nullptr, ldc,
                      Shi, splane, lds, nb * 128, rb);
}

// QKV fused: blockIdx.x selects q/k/v (co-scheduled -> A L2 reuse)
__global__ __launch_bounds__(256, 2) void qkv_cp_kernel(
    int lslot, const float* __restrict__ bq,
    const float* __restrict__ bk, const float* __restrict__ bv)
{
    extern __shared__ char dsm[];
    int which = blockIdx.x;
    int rb = blockIdx.y * 128;
    const __nv_bfloat16* Ws = g_Wt + (size_t)(lslot + which * 4) * SLOT_BF16;
    const float* bias = (which == 0) ? bq : (which == 1) ? bk : bv;
    float* C = (which == 0) ? g_Qb : (which == 1) ? g_Kb : g_Vb;
    gemm_cp_core<0>(dsm, g_Xs, DIM, (size_t)MTOT * DIM, Ws, 4, bias,
                    nullptr, nullptr, nullptr, C, DIM,
                    nullptr, 0, 0, 0, rb);
}

// ---------------------------------------------------------------------------
// Attention: one warp per 16x16 unit; writes ctx as split planes (g_Cs)
// ---------------------------------------------------------------------------
__global__ __launch_bounds__(256) void attn_kernel() {
    __shared__ float s_q[8][256];
    __shared__ float s_k[8][256];
    __shared__ float s_v[8][256];

    int w = threadIdx.x >> 5, lane = threadIdx.x & 31;
    size_t n = (size_t)blockIdx.x * 8 + w;
    size_t bse = n * 256;

    const float4* q4 = (const float4*)(g_Qb + bse);
    const float4* k4 = (const float4*)(g_Kb + bse);
    const float4* v4 = (const float4*)(g_Vb + bse);
    ((float4*)s_q[w])[lane]      = q4[lane];
    ((float4*)s_q[w])[lane + 32] = q4[lane + 32];
    ((float4*)s_k[w])[lane]      = k4[lane];
    ((float4*)s_k[w])[lane + 32] = k4[lane + 32];
    ((float4*)s_v[w])[lane]      = v4[lane];
    ((float4*)s_v[w])[lane + 32] = v4[lane + 32];
    __syncwarp();

    int i = lane >> 1;
    int jb = (lane & 1) * 8;

    float qr[16];
    #pragma unroll
    for (int u = 0; u < 4; u++) {
        float4 t4 = *(const float4*)&s_q[w][i * 16 + u * 4];
        qr[u * 4 + 0] = t4.x; qr[u * 4 + 1] = t4.y;
        qr[u * 4 + 2] = t4.z; qr[u * 4 + 3] = t4.w;
    }

    float sc[8];
    #pragma unroll
    for (int j = 0; j < 8; j++) {
        const float* kr = &s_k[w][(jb + j) * 16];
        float dd = 0.f;
        #pragma unroll
        for (int u = 0; u < 16; u++) dd = fmaf(qr[u], kr[u], dd);
        sc[j] = dd * 0.25f;
    }

    float mx = sc[0];
    #pragma unroll
    for (int j = 1; j < 8; j++) mx = fmaxf(mx, sc[j]);
    mx = fmaxf(mx, __shfl_xor_sync(0xffffffffu, mx, 1));

    float sum = 0.f;
    #pragma unroll
    for (int j = 0; j < 8; j++) { sc[j] = __expf(sc[j] - mx); sum += sc[j]; }
    sum += __shfl_xor_sync(0xffffffffu, sum, 1);
    float inv = 1.f / sum;

    float acc[16] = {};
    #pragma unroll
    for (int j = 0; j < 8; j++) {
        float p = sc[j] * inv;
        const float* vr = &s_v[w][(jb + j) * 16];
        #pragma unroll
        for (int u = 0; u < 16; u++) acc[u] = fmaf(p, vr[u], acc[u]);
    }
    #pragma unroll
    for (int u = 0; u < 16; u++)
        acc[u] += __shfl_xor_sync(0xffffffffu, acc[u], 1);

    int db = (lane & 1) * 8;
    uint32_t hw[4], lw[4];
    #pragma unroll
    for (int u2 = 0; u2 < 4; u2++)
        hw[u2] = split_pair(acc[db + u2 * 2], acc[db + u2 * 2 + 1], lw[u2]);
    const size_t PL = (size_t)MTOT * DIM;
    size_t e = bse + i * 16 + db;
    *(uint4*)(&g_Cs[e])      = make_uint4(hw[0], hw[1], hw[2], hw[3]);
    *(uint4*)(&g_Cs[PL + e]) = make_uint4(lw[0], lw[1], lw[2], lw[3]);
}

// ---------------------------------------------------------------------------
// Head
// ---------------------------------------------------------------------------
__global__ __launch_bounds__(128) void numproj_kernel(
    const float* __restrict__ num, const float* __restrict__ Wn,
    const float* __restrict__ bnum)
{
    __shared__ float sn[NUMF];
    int b = blockIdx.x, t = threadIdx.x;
    if (t < NUMF) sn[t] = num[(size_t)b * NUMF + t];
    __syncthreads();
    float acc = bnum[t];
    #pragma unroll 1
    for (int k = 0; k < NUMF; k++)
        acc = fmaf(sn[k], Wn[k * DIM + t], acc);
    g_Np[(size_t)b * DIM + t] = acc;
}

__global__ __launch_bounds__(256) void bn_partial_kernel() {
    int j = blockIdx.x, t = threadIdx.x;
    int col = t & 127, half = t >> 7;
    float s = 0.f, q = 0.f;
    for (int i = 0; i < 64; i++) {
        float v = g_Np[(size_t)(j * 128 + half * 64 + i) * DIM + col];
        s += v; q += v * v;
    }
    __shared__ float ss[256], sq[256];
    ss[t] = s; sq[t] = q;
    __syncthreads();
    if (half == 0) {
        g_bnp[j * DIM + col]            = ss[t] + ss[t + 128];
        g_bnp[64 * DIM + j * DIM + col] = sq[t] + sq[t + 128];
    }
}

__global__ __launch_bounds__(128) void bn_final_kernel(
    const float* __restrict__ gamma, const float* __restrict__ beta)
{
    int c = threadIdx.x;
    float s = 0.f, q = 0.f;
    for (int j = 0; j < 64; j++) {
        s += g_bnp[j * DIM + c];
        q += g_bnp[64 * DIM + j * DIM + c];
    }
    float mu = s * (1.f / 8192.f);
    float var = q * (1.f / 8192.f) - mu * mu;
    float a = gamma[c] * rsqrtf(var + EPSV);
    g_bns[c] = a;
    g_bns[DIM + c] = beta[c] - mu * a;
}

__global__ __launch_bounds__(256) void final_kernel(
    const float* __restrict__ gcn, const float* __restrict__ Wf,
    const float* __restrict__ bf, float* __restrict__ out)
{
    int b = blockIdx.x, t = threadIdx.x;
    const float* xr = g_X + (size_t)b * (SEQ * DIM);
    float acc = 0.f;
    #pragma unroll
    for (int i = 0; i < 8; i++) {
        int idx = t + 256 * i;
        acc = fmaf(xr[idx], Wf[idx], acc);
    }
    if (t < GCN)
        acc = fmaf(gcn[(size_t)b * GCN + t], Wf[SEQ * DIM + t], acc);
    if (t < DIM) {
        float v = g_Np[(size_t)b * DIM + t] * g_bns[t] + g_bns[DIM + t];
        acc = fmaf(v, Wf[SEQ * DIM + GCN + t], acc);
    }
    acc = warp_red(acc);
    __shared__ float red[8];
    if ((t & 31) == 0) red[t >> 5] = acc;
    __syncthreads();
    if (t == 0) {
        float z = red[0] + red[1] + red[2] + red[3]
                + red[4] + red[5] + red[6] + red[7] + bf[0];
        out[b] = 1.f / (1.f + expf(-z));
    }
}

// ---------------------------------------------------------------------------
// Launch
// ---------------------------------------------------------------------------
extern "C" void kernel_launch(void* const* d_in, const int* in_sizes, int n_in,
                              void* d_out, int out_size)
{
    const float* x    = (const float*)d_in[0];
    const float* gcn  = (const float*)d_in[1];
    const float* num  = (const float*)d_in[2];
    const float* Wq   = (const float*)d_in[3];
    const float* bq   = (const float*)d_in[4];
    const float* Wk   = (const float*)d_in[5];
    const float* bk   = (const float*)d_in[6];
    const float* Wv   = (const float*)d_in[7];
    const float* bv   = (const float*)d_in[8];
    const float* Wo   = (const float*)d_in[9];
    const float* bo   = (const float*)d_in[10];
    const float* ln1g = (const float*)d_in[11];
    const float* ln1b = (const float*)d_in[12];
    const float* W1   = (const float*)d_in[13];
    const float* b1   = (const float*)d_in[14];
    const float* W2   = (const float*)d_in[15];
    const float* b2   = (const float*)d_in[16];
    const float* ln2g = (const float*)d_in[17];
    const float* ln2b = (const float*)d_in[18];
    const float* Wn   = (const float*)d_in[19];
    const float* bnum = (const float*)d_in[20];
    const float* bng  = (const float*)d_in[21];
    const float* bnb  = (const float*)d_in[22];
    const float* Wf   = (const float*)d_in[23];
    const float* bf   = (const float*)d_in[24];
    float* out = (float*)d_out;

    cudaFuncSetAttribute(qkv_cp_kernel,
        cudaFuncAttributeMaxDynamicSharedMemorySize, DSMEM_BYTES);
    cudaFuncSetAttribute(gemm_cp_kernel<1>,
        cudaFuncAttributeMaxDynamicSharedMemorySize, DSMEM_BYTES);
    cudaFuncSetAttribute(gemm_cp_kernel<2>,
        cudaFuncAttributeMaxDynamicSharedMemorySize, DSMEM_BYTES);

    pe_init_kernel<<<2, 1024>>>();
    prep_weights_kernel<<<SLOTS_TOTAL, 256>>>(Wq, Wk, Wv, Wo, W1, W2);
    add_pe_kernel<<<16384, 256>>>(x);

    const int RB = MTOT / 128;   // 1024 row blocks
    for (int l = 0; l < 2; l++) {
        int lb = l * 80;
        // QKV: g_Xs -> Q,K,V (fp32)
        qkv_cp_kernel<<<dim3(3, RB), 256, DSMEM_BYTES>>>(
            lb, bq + l * DIM, bk + l * DIM, bv + l * DIM);
        // attention: fp32 q,k,v -> ctx split planes (g_Cs)
        attn_kernel<<<MTOT / 16, 256>>>();
        // h = LN(ctx @ Wo + bo + X): fp32 -> g_Kb, split -> g_Hs
        gemm_cp_kernel<2><<<dim3(1, RB), 256, DSMEM_BYTES>>>(
            1, DIM, lb + 12, 4, bo + l * DIM, 0,
            ln1g + l * DIM, ln1b + l * DIM, 2, DIM, 2, DIM);
        // ffn hidden = relu(h @ W1 + b1): split -> g_Fs
        gemm_cp_kernel<1><<<dim3(8, RB), 256, DSMEM_BYTES>>>(
            2, DIM, lb + 16, 4, b1 + l * HID, -1,
            nullptr, nullptr, -1, 0, 3, HID);
        // out = LN(ffn @ W2 + b2 + h): fp32 -> g_X, split -> g_Xs
        gemm_cp_kernel<2><<<dim3(1, RB), 256, DSMEM_BYTES>>>(
            3, HID, lb + 48, 32, b2 + l * DIM, 2,
            ln2g + l * DIM, ln2b + l * DIM, 0, DIM, 0, DIM);
    }

    numproj_kernel<<<BATCH, 128>>>(num, Wn, bnum);
    bn_partial_kernel<<<64, 256>>>();
    bn_final_kernel<<<1, 128>>>(bng, bnb);
    final_kernel<<<BATCH, 256>>>(gcn, Wf, bf, out);
}

// round 10
// speedup vs baseline: 3.3446x; 1.4396x over previous
#include <cuda_runtime.h>
#include <cuda_fp16.h>
#include <math.h>
#include <stdint.h>

// ---------------------------------------------------------------------------
// Problem constants
// ---------------------------------------------------------------------------
#define BATCH 8192
#define SEQ   16
#define DIM   128
#define MTOT  (BATCH * SEQ)        // 131072 rows
#define HID   1024
#define GCN   40
#define NUMF  103
#define EPSV  1e-5f

// Weight-tile store: each "slot" = one 128(N)x32(K) tile, fp16 hi then lo,
// SW64-swizzled 64B rows — ldmatrix-ready. 4096 fp16 per plane.
#define SLOT_ELE    8192             // hi(4096) + lo(4096) = 16KB
#define SLOTS_TOTAL 160              // 80 per layer x 2 layers
// per-layer map: Wq:0-3 Wk:4-7 Wv:8-11 Wo:12-15 W1:16+nb*4+kc W2:48+kc

// GEMM tile: M=128, N=128, Kchunk=32, 8 warps (256 thr), 2 CTAs/SM.
// stage = A 8K + B-hi 8K + B-lo 8K = 24KB, 3-stage ring.
#define KCH   32
#define OA    0u
#define OB_HI 8192u
#define STAGE_B 24576u
#define NSTAGE 3
#define DSMEM_BYTES (1024 + NSTAGE * STAGE_B)   // 74752

// ---------------------------------------------------------------------------
// Scratch (device globals: the sanctioned no-alloc workaround)
// ---------------------------------------------------------------------------
__device__ float g_X[MTOT * DIM];          // xpe / layer output (fp32)
__device__ float g_Qb[MTOT * DIM];         // q (fp32)
__device__ float g_Kb[MTOT * DIM];         // k, then h (fp32)
__device__ float g_Vb[MTOT * DIM];         // v (fp32)
__device__ float g_Np[BATCH * DIM];
__device__ float g_bnp[2 * 64 * DIM];
__device__ float g_bns[2 * DIM];
__device__ float g_PE[SEQ * DIM];
__device__ __half g_Wt[(size_t)SLOTS_TOTAL * SLOT_ELE];
// plain-fp16 activation planes (single plane each)
__device__ __half g_Xs[(size_t)MTOT * DIM];   // QKV input
__device__ __half g_Cs[(size_t)MTOT * DIM];   // ctx -> Wo input
__device__ __half g_Hs[(size_t)MTOT * DIM];   // h -> FFN1 input
__device__ __half g_Fs[(size_t)MTOT * HID];   // ffn hidden -> FFN2 input

__device__ __forceinline__ float* self32(int s) {
    switch (s) {
        case 0: return g_X;
        case 1: return g_Qb;
        case 2: return g_Kb;
        case 3: return g_Vb;
    }
    return nullptr;
}
__device__ __forceinline__ __half* selh(int s) {
    switch (s) {
        case 0: return g_Xs;
        case 1: return g_Cs;
        case 2: return g_Hs;
        case 3: return g_Fs;
    }
    return nullptr;
}

__device__ __forceinline__ float warp_red(float v) {
    #pragma unroll
    for (int o = 16; o; o >>= 1) v += __shfl_xor_sync(0xffffffffu, v, o);
    return v;
}

// ---------------------------------------------------------------------------
// PTX helpers (family-target-safe: ldmatrix sm_75+, mma/cp.async sm_80+)
// ---------------------------------------------------------------------------
__device__ __forceinline__ uint32_t smem_u32(const void* p) {
    uint32_t a;
    asm("{ .reg .u64 t; cvta.to.shared.u64 t, %1; cvt.u32.u64 %0, t; }"
        : "=r"(a) : "l"(p));
    return a;
}

__device__ __forceinline__ void ldm4(uint32_t* r, uint32_t addr) {
    asm volatile("ldmatrix.sync.aligned.m8n8.x4.shared.b16 {%0,%1,%2,%3}, [%4];"
                 : "=r"(r[0]), "=r"(r[1]), "=r"(r[2]), "=r"(r[3]) : "r"(addr));
}

__device__ __forceinline__ void mma16816h(float* c, const uint32_t* a,
                                          const uint32_t* b) {
    asm volatile(
        "mma.sync.aligned.m16n8k16.row.col.f32.f16.f16.f32 "
        "{%0,%1,%2,%3}, {%4,%5,%6,%7}, {%8,%9}, {%0,%1,%2,%3};"
        : "+f"(c[0]), "+f"(c[1]), "+f"(c[2]), "+f"(c[3])
        : "r"(a[0]), "r"(a[1]), "r"(a[2]), "r"(a[3]), "r"(b[0]), "r"(b[1]));
}

__device__ __forceinline__ void cpa16(uint32_t dst, const void* src) {
    asm volatile("{ .reg .u64 g; cvta.to.global.u64 g, %1; "
                 "cp.async.cg.shared.global [%0], [g], 16; }"
                 :: "r"(dst), "l"(src));
}
__device__ __forceinline__ void cp_commit() {
    asm volatile("cp.async.commit_group;" ::: "memory");
}
__device__ __forceinline__ void cp_wait0() {
    asm volatile("cp.async.wait_group 0;" ::: "memory");
}
__device__ __forceinline__ void cp_wait1() {
    asm volatile("cp.async.wait_group 1;" ::: "memory");
}

// SW64 swizzle for 64-byte rows
__device__ __forceinline__ uint32_t sw64(uint32_t off) {
    return off ^ ((off >> 3) & 0x30);
}

// pack two floats -> fp16x2 (RN)
__device__ __forceinline__ uint32_t pack_h2(float a, float b) {
    uint32_t h;
    asm("cvt.rn.f16x2.f32 %0, %1, %2;" : "=r"(h) : "f"(b), "f"(a));
    return h;
}
// split fp32 pair -> packed fp16x2 hi + lo residual
__device__ __forceinline__ uint32_t split_pair_h(float a, float b, uint32_t& lo) {
    uint32_t h = pack_h2(a, b);
    float ha = __half2float(__ushort_as_half((unsigned short)(h & 0xffffu)));
    float hb = __half2float(__ushort_as_half((unsigned short)(h >> 16)));
    lo = pack_h2(a - ha, b - hb);
    return h;
}

// ---------------------------------------------------------------------------
// PE init + add (also writes plain fp16 plane for QKV input)
// ---------------------------------------------------------------------------
__global__ void pe_init_kernel() {
    int idx = blockIdx.x * 1024 + threadIdx.x;
    if (idx < SEQ * DIM) {
        int s = idx >> 7, d = idx & 127;
        double e = (double)((d >> 1) * 2) / (double)DIM;
        double p = (double)s / pow(10000.0, e);
        g_PE[idx] = (float)((d & 1) ? cos(p) : sin(p));
    }
}

__global__ void add_pe_kernel(const float* __restrict__ x) {
    size_t i4 = (size_t)blockIdx.x * 256 + threadIdx.x;
    float4 xv = ((const float4*)x)[i4];
    int sd = (int)((i4 * 4) & 2047);
    float4 pv = *(const float4*)(g_PE + sd);
    xv.x += pv.x; xv.y += pv.y; xv.z += pv.z; xv.w += pv.w;
    ((float4*)g_X)[i4] = xv;
    *(uint2*)(&g_Xs[i4 * 4]) =
        make_uint2(pack_h2(xv.x, xv.y), pack_h2(xv.z, xv.w));
}

// ---------------------------------------------------------------------------
// Weight prep: transpose + fp16 split + SW64-swizzle into 128x32 tiles.
// ---------------------------------------------------------------------------
__global__ __launch_bounds__(256) void prep_weights_kernel(
    const float* __restrict__ Wq, const float* __restrict__ Wk,
    const float* __restrict__ Wv, const float* __restrict__ Wo,
    const float* __restrict__ W1, const float* __restrict__ W2)
{
    int slot = blockIdx.x;
    int l = slot / 80, s = slot % 80;
    const float* W; int Nmat, nb, kc;
    if (s < 16) {
        int m = s >> 2; kc = s & 3; nb = 0; Nmat = 128;
        const float* mats[4] = {Wq, Wk, Wv, Wo};
        W = mats[m] + (size_t)l * DIM * DIM;
    } else if (s < 48) {
        int t = s - 16; nb = t >> 2; kc = t & 3; Nmat = HID;
        W = W1 + (size_t)l * DIM * HID;
    } else {
        int t = s - 48; nb = 0; kc = t; Nmat = 128;
        W = W2 + (size_t)l * HID * DIM;
    }
    char* tile_hi = (char*)(g_Wt + (size_t)slot * SLOT_ELE);
    char* tile_lo = tile_hi + 8192;

    #pragma unroll
    for (int it = 0; it < 2; it++) {
        int g = it * 256 + threadIdx.x;    // 16B granule 0..511
        int n_local = g >> 2;
        int kq = (g & 3) * 8;
        uint4 hi4, lo4;
        uint32_t* hp = (uint32_t*)&hi4;
        uint32_t* lp = (uint32_t*)&lo4;
        #pragma unroll
        for (int u = 0; u < 4; u++) {
            float v0 = W[(size_t)(kc * 32 + kq + u * 2 + 0) * Nmat + nb * 128 + n_local];
            float v1 = W[(size_t)(kc * 32 + kq + u * 2 + 1) * Nmat + nb * 128 + n_local];
            hp[u] = split_pair_h(v0, v1, lp[u]);
        }
        uint32_t sw = sw64((uint32_t)(n_local * 64 + kq * 2));
        *(uint4*)(tile_hi + sw) = hi4;
        *(uint4*)(tile_lo + sw) = lo4;
    }
}

// ---------------------------------------------------------------------------
// cp.async 3-stage GEMM core. Tile 128x128, 8 warps, Kchunk=32.
// warp: wm = wid&1 -> rows wm*64+[0,64); wn = wid>>1 -> cols wn*32+[0,32).
// 2-product fp16: A(fp16)*Bhi + A(fp16)*Blo   (B split; err = A rounding)
// EPI: 0 = bias -> fp32 C; 1 = bias+relu -> fp16 plane;
//      2 = bias+residual+LN -> fp32 C AND fp16 plane
// ---------------------------------------------------------------------------
template <int EPI>
__device__ __forceinline__ void gemm_cp_core(
    char* dsm_raw,
    const __half* __restrict__ A, int lda,
    const __half* __restrict__ Wslots, int nchunks,
    const float* __restrict__ bias,
    const float* __restrict__ R,
    const float* __restrict__ gam, const float* __restrict__ bet,
    float* __restrict__ C, int ldc,
    __half* __restrict__ Sh, int lds,
    int ncoloff, int rb)
{
    __shared__ float s_sp[128][4];
    __shared__ float s_sq[128][4];

    uint32_t raw_u = smem_u32(dsm_raw);
    uint32_t sbase = (raw_u + 1023) & ~1023u;

    int tid = threadIdx.x;
    int wid = tid >> 5, lane = tid & 31;
    int wm = wid & 1, wn = wid >> 1;

    // ldmatrix lane geometry
    int mt = lane >> 3;
    int rr = lane & 7;
    int row_off = ((mt & 1) << 3) + rr;
    int kk_off = (mt >> 1) << 3;

    // hoisted loader geometry: 2 A granules + 4 B granules per thread
    uint32_t ag_sw[2];
    const __half* ag_src[2];
    #pragma unroll
    for (int p = 0; p < 2; p++) {
        int g = p * 256 + tid;             // 0..511
        int arow = g >> 2, kq = (g & 3) * 8;
        ag_sw[p] = sw64((uint32_t)(arow * 64 + kq * 2));
        ag_src[p] = A + (size_t)(rb + arow) * lda + kq;
    }
    const char* bbase = (const char*)Wslots;

    float acc[4][4][4];
    #pragma unroll
    for (int i = 0; i < 4; i++)
        #pragma unroll
        for (int j = 0; j < 4; j++)
            #pragma unroll
            for (int r = 0; r < 4; r++) acc[i][j][r] = 0.f;

    auto issue = [&](int buf, int c) {
        uint32_t st = sbase + buf * STAGE_B;
        #pragma unroll
        for (int p = 0; p < 2; p++)
            cpa16(st + OA + ag_sw[p], ag_src[p] + c * KCH);
        // B slot: 16KB straight copy (hi 8KB then lo 8KB, pre-swizzled)
        const char* bs = bbase + (size_t)c * (SLOT_ELE * 2);
        #pragma unroll
        for (int p = 0; p < 4; p++) {
            uint32_t off = (uint32_t)((p * 256 + tid) * 16);
            cpa16(st + OB_HI + off, bs + off);
        }
    };

    issue(0, 0);
    cp_commit();
    if (nchunks > 1) { issue(1, 1); cp_commit(); }

    for (int c = 0; c < nchunks; c++) {
        if (c + 1 < nchunks) cp_wait1(); else cp_wait0();
        __syncthreads();
        if (c + 2 < nchunks) { issue((c + 2) % NSTAGE, c + 2); cp_commit(); }

        uint32_t st = sbase + (c % NSTAGE) * STAGE_B;
        #pragma unroll
        for (int k16 = 0; k16 < 2; k16++) {
            int kbase = k16 * 16 + kk_off;
            // B fragments (hi + lo)
            uint32_t bh[4][2], bl[4][2];
            #pragma unroll
            for (int in2 = 0; in2 < 2; in2++) {
                int nrow = wn * 32 + in2 * 16 + row_off;
                uint32_t off = sw64((uint32_t)(nrow * 64 + kbase * 2));
                uint32_t t[4];
                ldm4(t, st + OB_HI + off);
                bh[in2 * 2 + 0][0] = t[0]; bh[in2 * 2 + 0][1] = t[2];
                bh[in2 * 2 + 1][0] = t[1]; bh[in2 * 2 + 1][1] = t[3];
                ldm4(t, st + OB_HI + 8192u + off);
                bl[in2 * 2 + 0][0] = t[0]; bl[in2 * 2 + 0][1] = t[2];
                bl[in2 * 2 + 1][0] = t[1]; bl[in2 * 2 + 1][1] = t[3];
            }
            // A fragments (plain fp16)
            uint32_t af[4][4];
            #pragma unroll
            for (int im = 0; im < 4; im++) {
                int mrow = wm * 64 + im * 16 + row_off;
                ldm4(af[im], st + OA + sw64((uint32_t)(mrow * 64 + kbase * 2)));
            }
            // two product sweeps
            #pragma unroll
            for (int im = 0; im < 4; im++)
                #pragma unroll
                for (int in = 0; in < 4; in++)
                    mma16816h(acc[im][in], af[im], bh[in]);
            #pragma unroll
            for (int im = 0; im < 4; im++)
                #pragma unroll
                for (int in = 0; in < 4; in++)
                    mma16816h(acc[im][in], af[im], bl[in]);
        }
        __syncthreads();
    }

    // ---- epilogue ----
    int r_in = lane >> 2;
    int c_in = (lane & 3) * 2;

    if (EPI == 0) {
        #pragma unroll
        for (int im = 0; im < 4; im++) {
            size_t gr0 = (size_t)(rb + wm * 64 + im * 16 + r_in);
            #pragma unroll
            for (int in = 0; in < 4; in++) {
                int cl = wn * 32 + in * 8 + c_in;
                float b0 = bias[cl], b1 = bias[cl + 1];
                *(float2*)(C + gr0 * ldc + ncoloff + cl) =
                    make_float2(acc[im][in][0] + b0, acc[im][in][1] + b1);
                *(float2*)(C + (gr0 + 8) * ldc + ncoloff + cl) =
                    make_float2(acc[im][in][2] + b0, acc[im][in][3] + b1);
            }
        }
    } else if (EPI == 1) {
        #pragma unroll
        for (int im = 0; im < 4; im++) {
            size_t gr0 = (size_t)(rb + wm * 64 + im * 16 + r_in);
            #pragma unroll
            for (int in = 0; in < 4; in++) {
                int cl = wn * 32 + in * 8 + c_in;
                float b0 = bias[cl], b1 = bias[cl + 1];
                float v0 = fmaxf(acc[im][in][0] + b0, 0.f);
                float v1 = fmaxf(acc[im][in][1] + b1, 0.f);
                float v2 = fmaxf(acc[im][in][2] + b0, 0.f);
                float v3 = fmaxf(acc[im][in][3] + b1, 0.f);
                *(uint32_t*)&Sh[gr0 * lds + ncoloff + cl] = pack_h2(v0, v1);
                *(uint32_t*)&Sh[(gr0 + 8) * lds + ncoloff + cl] = pack_h2(v2, v3);
            }
        }
    } else {
        float sv[4][2] = {}, qv[4][2] = {};
        #pragma unroll
        for (int im = 0; im < 4; im++) {
            size_t gr0 = (size_t)(rb + wm * 64 + im * 16 + r_in);
            #pragma unroll
            for (int in = 0; in < 4; in++) {
                int cl = wn * 32 + in * 8 + c_in;
                float b0 = bias[cl], b1 = bias[cl + 1];
                float2 rv0 = *(const float2*)(R + gr0 * DIM + cl);
                float2 rv1 = *(const float2*)(R + (gr0 + 8) * DIM + cl);
                float v0 = acc[im][in][0] + b0 + rv0.x;
                float v1 = acc[im][in][1] + b1 + rv0.y;
                float v2 = acc[im][in][2] + b0 + rv1.x;
                float v3 = acc[im][in][3] + b1 + rv1.y;
                acc[im][in][0] = v0; acc[im][in][1] = v1;
                acc[im][in][2] = v2; acc[im][in][3] = v3;
                sv[im][0] += v0 + v1; qv[im][0] += v0 * v0 + v1 * v1;
                sv[im][1] += v2 + v3; qv[im][1] += v2 * v2 + v3 * v3;
            }
        }
        #pragma unroll
        for (int im = 0; im < 4; im++)
            #pragma unroll
            for (int h2 = 0; h2 < 2; h2++) {
                float s = sv[im][h2], q = qv[im][h2];
                s += __shfl_xor_sync(0xffffffffu, s, 1);
                s += __shfl_xor_sync(0xffffffffu, s, 2);
                q += __shfl_xor_sync(0xffffffffu, q, 1);
                q += __shfl_xor_sync(0xffffffffu, q, 2);
                if ((lane & 3) == 0) {
                    int rl = wm * 64 + im * 16 + r_in + h2 * 8;
                    s_sp[rl][wn] = s;
                    s_sq[rl][wn] = q;
                }
            }
        __syncthreads();
        float mn[4][2], rs[4][2];
        #pragma unroll
        for (int im = 0; im < 4; im++)
            #pragma unroll
            for (int h2 = 0; h2 < 2; h2++) {
                int rl = wm * 64 + im * 16 + r_in + h2 * 8;
                float s = s_sp[rl][0] + s_sp[rl][1] + s_sp[rl][2] + s_sp[rl][3];
                float q = s_sq[rl][0] + s_sq[rl][1] + s_sq[rl][2] + s_sq[rl][3];
                float m = s * (1.f / 128.f);
                float var = q * (1.f / 128.f) - m * m;
                mn[im][h2] = m;
                rs[im][h2] = rsqrtf(var + EPSV);
            }
        #pragma unroll
        for (int im = 0; im < 4; im++) {
            size_t gr0 = (size_t)(rb + wm * 64 + im * 16 + r_in);
            #pragma unroll
            for (int in = 0; in < 4; in++) {
                int cl = wn * 32 + in * 8 + c_in;
                float g0 = gam[cl], g1 = gam[cl + 1];
                float e0 = bet[cl], e1 = bet[cl + 1];
                float o0 = (acc[im][in][0] - mn[im][0]) * rs[im][0] * g0 + e0;
                float o1 = (acc[im][in][1] - mn[im][0]) * rs[im][0] * g1 + e1;
                float o2 = (acc[im][in][2] - mn[im][1]) * rs[im][1] * g0 + e0;
                float o3 = (acc[im][in][3] - mn[im][1]) * rs[im][1] * g1 + e1;
                *(float2*)(C + gr0 * ldc + cl) = make_float2(o0, o1);
                *(float2*)(C + (gr0 + 8) * ldc + cl) = make_float2(o2, o3);
                *(uint32_t*)&Sh[gr0 * lds + cl] = pack_h2(o0, o1);
                *(uint32_t*)&Sh[(gr0 + 8) * lds + cl] = pack_h2(o2, o3);
            }
        }
    }
}

// Generic GEMM kernel: blockIdx.x = col block, blockIdx.y = row block (128)
template <int EPI>
__global__ __launch_bounds__(256, 2) void gemm_cp_kernel(
    int absel, int lda, int slotbase, int kchunks,
    const float* __restrict__ bias, int rsel,
    const float* __restrict__ gam, const float* __restrict__ bet,
    int csel, int ldc, int ssel, int lds)
{
    extern __shared__ char dsm[];
    int nb = blockIdx.x;
    int rb = blockIdx.y * 128;
    const __half* Ah = selh(absel);
    __half* Sh = (ssel >= 0) ? selh(ssel) : nullptr;
    const __half* Ws =
        g_Wt + ((size_t)slotbase + (size_t)nb * kchunks) * SLOT_ELE;
    gemm_cp_core<EPI>(dsm, Ah, lda, Ws, kchunks,
                      bias + nb * 128,
                      rsel >= 0 ? self32(rsel) : nullptr, gam, bet,
                      csel >= 0 ? self32(csel) : nullptr, ldc,
                      Sh, lds, nb * 128, rb);
}

// QKV fused: blockIdx.x selects q/k/v (co-scheduled -> A L2 reuse)
__global__ __launch_bounds__(256, 2) void qkv_cp_kernel(
    int lslot, const float* __restrict__ bq,
    const float* __restrict__ bk, const float* __restrict__ bv)
{
    extern __shared__ char dsm[];
    int which = blockIdx.x;
    int rb = blockIdx.y * 128;
    const __half* Ws = g_Wt + (size_t)(lslot + which * 4) * SLOT_ELE;
    const float* bias = (which == 0) ? bq : (which == 1) ? bk : bv;
    float* C = (which == 0) ? g_Qb : (which == 1) ? g_Kb : g_Vb;
    gemm_cp_core<0>(dsm, g_Xs, DIM, Ws, 4, bias,
                    nullptr, nullptr, nullptr, C, DIM,
                    nullptr, 0, 0, rb);
}

// ---------------------------------------------------------------------------
// Attention: one warp per 16x16 unit; writes ctx as plain fp16 (g_Cs)
// ---------------------------------------------------------------------------
__global__ __launch_bounds__(256) void attn_kernel() {
    __shared__ float s_q[8][256];
    __shared__ float s_k[8][256];
    __shared__ float s_v[8][256];

    int w = threadIdx.x >> 5, lane = threadIdx.x & 31;
    size_t n = (size_t)blockIdx.x * 8 + w;
    size_t bse = n * 256;

    const float4* q4 = (const float4*)(g_Qb + bse);
    const float4* k4 = (const float4*)(g_Kb + bse);
    const float4* v4 = (const float4*)(g_Vb + bse);
    ((float4*)s_q[w])[lane]      = q4[lane];
    ((float4*)s_q[w])[lane + 32] = q4[lane + 32];
    ((float4*)s_k[w])[lane]      = k4[lane];
    ((float4*)s_k[w])[lane + 32] = k4[lane + 32];
    ((float4*)s_v[w])[lane]      = v4[lane];
    ((float4*)s_v[w])[lane + 32] = v4[lane + 32];
    __syncwarp();

    int i = lane >> 1;
    int jb = (lane & 1) * 8;

    float qr[16];
    #pragma unroll
    for (int u = 0; u < 4; u++) {
        float4 t4 = *(const float4*)&s_q[w][i * 16 + u * 4];
        qr[u * 4 + 0] = t4.x; qr[u * 4 + 1] = t4.y;
        qr[u * 4 + 2] = t4.z; qr[u * 4 + 3] = t4.w;
    }

    float sc[8];
    #pragma unroll
    for (int j = 0; j < 8; j++) {
        const float* kr = &s_k[w][(jb + j) * 16];
        float dd = 0.f;
        #pragma unroll
        for (int u = 0; u < 16; u++) dd = fmaf(qr[u], kr[u], dd);
        sc[j] = dd * 0.25f;
    }

    float mx = sc[0];
    #pragma unroll
    for (int j = 1; j < 8; j++) mx = fmaxf(mx, sc[j]);
    mx = fmaxf(mx, __shfl_xor_sync(0xffffffffu, mx, 1));

    float sum = 0.f;
    #pragma unroll
    for (int j = 0; j < 8; j++) { sc[j] = __expf(sc[j] - mx); sum += sc[j]; }
    sum += __shfl_xor_sync(0xffffffffu, sum, 1);
    float inv = 1.f / sum;

    float acc[16] = {};
    #pragma unroll
    for (int j = 0; j < 8; j++) {
        float p = sc[j] * inv;
        const float* vr = &s_v[w][(jb + j) * 16];
        #pragma unroll
        for (int u = 0; u < 16; u++) acc[u] = fmaf(p, vr[u], acc[u]);
    }
    #pragma unroll
    for (int u = 0; u < 16; u++)
        acc[u] += __shfl_xor_sync(0xffffffffu, acc[u], 1);

    int db = (lane & 1) * 8;
    size_t e = bse + i * 16 + db;
    *(uint4*)(&g_Cs[e]) = make_uint4(
        pack_h2(acc[db + 0], acc[db + 1]), pack_h2(acc[db + 2], acc[db + 3]),
        pack_h2(acc[db + 4], acc[db + 5]), pack_h2(acc[db + 6], acc[db + 7]));
}

// ---------------------------------------------------------------------------
// Head
// ---------------------------------------------------------------------------
__global__ __launch_bounds__(128) void numproj_kernel(
    const float* __restrict__ num, const float* __restrict__ Wn,
    const float* __restrict__ bnum)
{
    __shared__ float sn[NUMF];
    int b = blockIdx.x, t = threadIdx.x;
    if (t < NUMF) sn[t] = num[(size_t)b * NUMF + t];
    __syncthreads();
    float acc = bnum[t];
    #pragma unroll 1
    for (int k = 0; k < NUMF; k++)
        acc = fmaf(sn[k], Wn[k * DIM + t], acc);
    g_Np[(size_t)b * DIM + t] = acc;
}

__global__ __launch_bounds__(256) void bn_partial_kernel() {
    int j = blockIdx.x, t = threadIdx.x;
    int col = t & 127, half = t >> 7;
    float s = 0.f, q = 0.f;
    for (int i = 0; i < 64; i++) {
        float v = g_Np[(size_t)(j * 128 + half * 64 + i) * DIM + col];
        s += v; q += v * v;
    }
    __shared__ float ss[256], sq[256];
    ss[t] = s; sq[t] = q;
    __syncthreads();
    if (half == 0) {
        g_bnp[j * DIM + col]            = ss[t] + ss[t + 128];
        g_bnp[64 * DIM + j * DIM + col] = sq[t] + sq[t + 128];
    }
}

__global__ __launch_bounds__(128) void bn_final_kernel(
    const float* __restrict__ gamma, const float* __restrict__ beta)
{
    int c = threadIdx.x;
    float s = 0.f, q = 0.f;
    for (int j = 0; j < 64; j++) {
        s += g_bnp[j * DIM + c];
        q += g_bnp[64 * DIM + j * DIM + c];
    }
    float mu = s * (1.f / 8192.f);
    float var = q * (1.f / 8192.f) - mu * mu;
    float a = gamma[c] * rsqrtf(var + EPSV);
    g_bns[c] = a;
    g_bns[DIM + c] = beta[c] - mu * a;
}

__global__ __launch_bounds__(256) void final_kernel(
    const float* __restrict__ gcn, const float* __restrict__ Wf,
    const float* __restrict__ bf, float* __restrict__ out)
{
    int b = blockIdx.x, t = threadIdx.x;
    const float* xr = g_X + (size_t)b * (SEQ * DIM);
    float acc = 0.f;
    #pragma unroll
    for (int i = 0; i < 8; i++) {
        int idx = t + 256 * i;
        acc = fmaf(xr[idx], Wf[idx], acc);
    }
    if (t < GCN)
        acc = fmaf(gcn[(size_t)b * GCN + t], Wf[SEQ * DIM + t], acc);
    if (t < DIM) {
        float v = g_Np[(size_t)b * DIM + t] * g_bns[t] + g_bns[DIM + t];
        acc = fmaf(v, Wf[SEQ * DIM + GCN + t], acc);
    }
    acc = warp_red(acc);
    __shared__ float red[8];
    if ((t & 31) == 0) red[t >> 5] = acc;
    __syncthreads();
    if (t == 0) {
        float z = red[0] + red[1] + red[2] + red[3]
                + red[4] + red[5] + red[6] + red[7] + bf[0];
        out[b] = 1.f / (1.f + expf(-z));
    }
}

// ---------------------------------------------------------------------------
// Launch
// ---------------------------------------------------------------------------
extern "C" void kernel_launch(void* const* d_in, const int* in_sizes, int n_in,
                              void* d_out, int out_size)
{
    const float* x    = (const float*)d_in[0];
    const float* gcn  = (const float*)d_in[1];
    const float* num  = (const float*)d_in[2];
    const float* Wq   = (const float*)d_in[3];
    const float* bq   = (const float*)d_in[4];
    const float* Wk   = (const float*)d_in[5];
    const float* bk   = (const float*)d_in[6];
    const float* Wv   = (const float*)d_in[7];
    const float* bv   = (const float*)d_in[8];
    const float* Wo   = (const float*)d_in[9];
    const float* bo   = (const float*)d_in[10];
    const float* ln1g = (const float*)d_in[11];
    const float* ln1b = (const float*)d_in[12];
    const float* W1   = (const float*)d_in[13];
    const float* b1   = (const float*)d_in[14];
    const float* W2   = (const float*)d_in[15];
    const float* b2   = (const float*)d_in[16];
    const float* ln2g = (const float*)d_in[17];
    const float* ln2b = (const float*)d_in[18];
    const float* Wn   = (const float*)d_in[19];
    const float* bnum = (const float*)d_in[20];
    const float* bng  = (const float*)d_in[21];
    const float* bnb  = (const float*)d_in[22];
    const float* Wf   = (const float*)d_in[23];
    const float* bf   = (const float*)d_in[24];
    float* out = (float*)d_out;

    cudaFuncSetAttribute(qkv_cp_kernel,
        cudaFuncAttributeMaxDynamicSharedMemorySize, DSMEM_BYTES);
    cudaFuncSetAttribute(gemm_cp_kernel<1>,
        cudaFuncAttributeMaxDynamicSharedMemorySize, DSMEM_BYTES);
    cudaFuncSetAttribute(gemm_cp_kernel<2>,
        cudaFuncAttributeMaxDynamicSharedMemorySize, DSMEM_BYTES);

    pe_init_kernel<<<2, 1024>>>();
    prep_weights_kernel<<<SLOTS_TOTAL, 256>>>(Wq, Wk, Wv, Wo, W1, W2);
    add_pe_kernel<<<16384, 256>>>(x);

    const int RB = MTOT / 128;   // 1024 row blocks
    for (int l = 0; l < 2; l++) {
        int lb = l * 80;
        // QKV: g_Xs -> Q,K,V (fp32)
        qkv_cp_kernel<<<dim3(3, RB), 256, DSMEM_BYTES>>>(
            lb, bq + l * DIM, bk + l * DIM, bv + l * DIM);
        // attention: fp32 q,k,v -> ctx fp16 (g_Cs)
        attn_kernel<<<MTOT / 16, 256>>>();
        // h = LN(ctx @ Wo + bo + X): fp32 -> g_Kb, fp16 -> g_Hs
        gemm_cp_kernel<2><<<dim3(1, RB), 256, DSMEM_BYTES>>>(
            1, DIM, lb + 12, 4, bo + l * DIM, 0,
            ln1g + l * DIM, ln1b + l * DIM, 2, DIM, 2, DIM);
        // ffn hidden = relu(h @ W1 + b1): fp16 -> g_Fs
        gemm_cp_kernel<1><<<dim3(8, RB), 256, DSMEM_BYTES>>>(
            2, DIM, lb + 16, 4, b1 + l * HID, -1,
            nullptr, nullptr, -1, 0, 3, HID);
        // out = LN(ffn @ W2 + b2 + h): fp32 -> g_X, fp16 -> g_Xs
        gemm_cp_kernel<2><<<dim3(1, RB), 256, DSMEM_BYTES>>>(
            3, HID, lb + 48, 32, b2 + l * DIM, 2,
            ln2g + l * DIM, ln2b + l * DIM, 0, DIM, 0, DIM);
    }

    numproj_kernel<<<BATCH, 128>>>(num, Wn, bnum);
    bn_partial_kernel<<<64, 256>>>();
    bn_final_kernel<<<1, 128>>>(bng, bnb);
    final_kernel<<<BATCH, 256>>>(gcn, Wf, bf, out);
}

// round 11
// speedup vs baseline: 4.1568x; 1.2428x over previous
#include <cuda_runtime.h>
#include <cuda_fp16.h>
#include <math.h>
#include <stdint.h>

// ---------------------------------------------------------------------------
// Problem constants
// ---------------------------------------------------------------------------
#define BATCH 8192
#define SEQ   16
#define DIM   128
#define MTOT  (BATCH * SEQ)        // 131072 rows
#define HID   1024
#define GCN   40
#define NUMF  103
#define EPSV  1e-5f

// Weight-tile store: each "slot" = one 128(N)x32(K) fp16 tile,
// SW64-swizzled 64B rows — ldmatrix-ready. 4096 fp16 = 8KB.
#define SLOT_ELE    4096
#define SLOTS_TOTAL 160              // 80 per layer x 2 layers
// per-layer map: Wq:0-3 Wk:4-7 Wv:8-11 Wo:12-15 W1:16+nb*4+kc W2:48+kc

// GEMM tile: M=128, N=128, Kchunk=32, 8 warps (256 thr), 2 CTAs/SM.
// stage = A 8K + B 8K = 16KB, 3-stage ring.
#define KCH   32
#define OA    0u
#define OB    8192u
#define STAGE_B 16384u
#define NSTAGE 3
#define DSMEM_BYTES (1024 + NSTAGE * STAGE_B)   // 50176

// ---------------------------------------------------------------------------
// Scratch (device globals: the sanctioned no-alloc workaround)
// ---------------------------------------------------------------------------
__device__ float g_X[MTOT * DIM];          // xpe / layer output (fp32)
__device__ float g_Kb[MTOT * DIM];         // h (fp32 residual for FFN2-LN)
__device__ float g_Np[BATCH * DIM];
__device__ float g_bnp[2 * 64 * DIM];
__device__ float g_bns[2 * DIM];
__device__ float g_PE[SEQ * DIM];
__device__ __half g_Wt[(size_t)SLOTS_TOTAL * SLOT_ELE];
// fp16 activation planes
__device__ __half g_Xs[(size_t)MTOT * DIM];   // QKV input
__device__ __half g_Cs[(size_t)MTOT * DIM];   // ctx -> Wo input
__device__ __half g_Hs[(size_t)MTOT * DIM];   // h -> FFN1 input
__device__ __half g_Fs[(size_t)MTOT * HID];   // ffn hidden -> FFN2 input
__device__ __half g_Qh[(size_t)MTOT * DIM];   // q
__device__ __half g_Kh[(size_t)MTOT * DIM];   // k
__device__ __half g_Vh[(size_t)MTOT * DIM];   // v

__device__ __forceinline__ float* self32(int s) {
    switch (s) {
        case 0: return g_X;
        case 2: return g_Kb;
    }
    return nullptr;
}
__device__ __forceinline__ __half* selh(int s) {
    switch (s) {
        case 0: return g_Xs;
        case 1: return g_Cs;
        case 2: return g_Hs;
        case 3: return g_Fs;
        case 4: return g_Qh;
        case 5: return g_Kh;
        case 6: return g_Vh;
    }
    return nullptr;
}

__device__ __forceinline__ float warp_red(float v) {
    #pragma unroll
    for (int o = 16; o; o >>= 1) v += __shfl_xor_sync(0xffffffffu, v, o);
    return v;
}

// ---------------------------------------------------------------------------
// PTX helpers (family-target-safe: ldmatrix sm_75+, mma/cp.async sm_80+)
// ---------------------------------------------------------------------------
__device__ __forceinline__ uint32_t smem_u32(const void* p) {
    uint32_t a;
    asm("{ .reg .u64 t; cvta.to.shared.u64 t, %1; cvt.u32.u64 %0, t; }"
        : "=r"(a) : "l"(p));
    return a;
}

__device__ __forceinline__ void ldm4(uint32_t* r, uint32_t addr) {
    asm volatile("ldmatrix.sync.aligned.m8n8.x4.shared.b16 {%0,%1,%2,%3}, [%4];"
                 : "=r"(r[0]), "=r"(r[1]), "=r"(r[2]), "=r"(r[3]) : "r"(addr));
}

__device__ __forceinline__ void mma16816h(float* c, const uint32_t* a,
                                          const uint32_t* b) {
    asm volatile(
        "mma.sync.aligned.m16n8k16.row.col.f32.f16.f16.f32 "
        "{%0,%1,%2,%3}, {%4,%5,%6,%7}, {%8,%9}, {%0,%1,%2,%3};"
        : "+f"(c[0]), "+f"(c[1]), "+f"(c[2]), "+f"(c[3])
        : "r"(a[0]), "r"(a[1]), "r"(a[2]), "r"(a[3]), "r"(b[0]), "r"(b[1]));
}

__device__ __forceinline__ void cpa16(uint32_t dst, const void* src) {
    asm volatile("{ .reg .u64 g; cvta.to.global.u64 g, %1; "
                 "cp.async.cg.shared.global [%0], [g], 16; }"
                 :: "r"(dst), "l"(src));
}
__device__ __forceinline__ void cp_commit() {
    asm volatile("cp.async.commit_group;" ::: "memory");
}
__device__ __forceinline__ void cp_wait0() {
    asm volatile("cp.async.wait_group 0;" ::: "memory");
}
__device__ __forceinline__ void cp_wait1() {
    asm volatile("cp.async.wait_group 1;" ::: "memory");
}

// SW64 swizzle for 64-byte rows
__device__ __forceinline__ uint32_t sw64(uint32_t off) {
    return off ^ ((off >> 3) & 0x30);
}

// pack two floats -> fp16x2 (RN)
__device__ __forceinline__ uint32_t pack_h2(float a, float b) {
    uint32_t h;
    asm("cvt.rn.f16x2.f32 %0, %1, %2;" : "=r"(h) : "f"(b), "f"(a));
    return h;
}

// ---------------------------------------------------------------------------
// PE init + add (writes fp32 and fp16 planes)
// ---------------------------------------------------------------------------
__global__ void pe_init_kernel() {
    int idx = blockIdx.x * 1024 + threadIdx.x;
    if (idx < SEQ * DIM) {
        int s = idx >> 7, d = idx & 127;
        double e = (double)((d >> 1) * 2) / (double)DIM;
        double p = (double)s / pow(10000.0, e);
        g_PE[idx] = (float)((d & 1) ? cos(p) : sin(p));
    }
}

__global__ void add_pe_kernel(const float* __restrict__ x) {
    size_t i4 = (size_t)blockIdx.x * 256 + threadIdx.x;
    float4 xv = ((const float4*)x)[i4];
    int sd = (int)((i4 * 4) & 2047);
    float4 pv = *(const float4*)(g_PE + sd);
    xv.x += pv.x; xv.y += pv.y; xv.z += pv.z; xv.w += pv.w;
    ((float4*)g_X)[i4] = xv;
    *(uint2*)(&g_Xs[i4 * 4]) =
        make_uint2(pack_h2(xv.x, xv.y), pack_h2(xv.z, xv.w));
}

// ---------------------------------------------------------------------------
// Weight prep: transpose + fp16 + SW64-swizzle into 128x32 tiles.
// ---------------------------------------------------------------------------
__global__ __launch_bounds__(256) void prep_weights_kernel(
    const float* __restrict__ Wq, const float* __restrict__ Wk,
    const float* __restrict__ Wv, const float* __restrict__ Wo,
    const float* __restrict__ W1, const float* __restrict__ W2)
{
    int slot = blockIdx.x;
    int l = slot / 80, s = slot % 80;
    const float* W; int Nmat, nb, kc;
    if (s < 16) {
        int m = s >> 2; kc = s & 3; nb = 0; Nmat = 128;
        const float* mats[4] = {Wq, Wk, Wv, Wo};
        W = mats[m] + (size_t)l * DIM * DIM;
    } else if (s < 48) {
        int t = s - 16; nb = t >> 2; kc = t & 3; Nmat = HID;
        W = W1 + (size_t)l * DIM * HID;
    } else {
        int t = s - 48; nb = 0; kc = t; Nmat = 128;
        W = W2 + (size_t)l * HID * DIM;
    }
    char* tile = (char*)(g_Wt + (size_t)slot * SLOT_ELE);

    {
        int g = threadIdx.x;               // 16B granule 0..511 (2 per thread)
        #pragma unroll
        for (int it = 0; it < 2; it++, g += 256) {
            int n_local = g >> 2;
            int kq = (g & 3) * 8;
            uint4 hi4;
            uint32_t* hp = (uint32_t*)&hi4;
            #pragma unroll
            for (int u = 0; u < 4; u++) {
                float v0 = W[(size_t)(kc * 32 + kq + u * 2 + 0) * Nmat + nb * 128 + n_local];
                float v1 = W[(size_t)(kc * 32 + kq + u * 2 + 1) * Nmat + nb * 128 + n_local];
                hp[u] = pack_h2(v0, v1);
            }
            uint32_t sw = sw64((uint32_t)(n_local * 64 + kq * 2));
            *(uint4*)(tile + sw) = hi4;
        }
    }
}

// ---------------------------------------------------------------------------
// cp.async 3-stage GEMM core. Tile 128x128, 8 warps, Kchunk=32.
// warp: wm = wid&1 -> rows wm*64+[0,64); wn = wid>>1 -> cols wn*32+[0,32).
// Single-product plain fp16 (fp32 accum).
// EPI: 0 = bias -> fp16 plane; 1 = bias+relu -> fp16 plane;
//      2 = bias+residual+LN -> fp32 C AND fp16 plane
// ---------------------------------------------------------------------------
template <int EPI>
__device__ __forceinline__ void gemm_cp_core(
    char* dsm_raw,
    const __half* __restrict__ A, int lda,
    const __half* __restrict__ Wslots, int nchunks,
    const float* __restrict__ bias,
    const float* __restrict__ R,
    const float* __restrict__ gam, const float* __restrict__ bet,
    float* __restrict__ C, int ldc,
    __half* __restrict__ Sh, int lds,
    int ncoloff, int rb)
{
    __shared__ float s_sp[128][4];
    __shared__ float s_sq[128][4];

    uint32_t raw_u = smem_u32(dsm_raw);
    uint32_t sbase = (raw_u + 1023) & ~1023u;

    int tid = threadIdx.x;
    int wid = tid >> 5, lane = tid & 31;
    int wm = wid & 1, wn = wid >> 1;

    // ldmatrix lane geometry
    int mt = lane >> 3;
    int rr = lane & 7;
    int row_off = ((mt & 1) << 3) + rr;
    int kk_off = (mt >> 1) << 3;

    // hoisted loader geometry: 2 A granules + 2 B granules per thread
    uint32_t ag_sw[2];
    const __half* ag_src[2];
    #pragma unroll
    for (int p = 0; p < 2; p++) {
        int g = p * 256 + tid;             // 0..511
        int arow = g >> 2, kq = (g & 3) * 8;
        ag_sw[p] = sw64((uint32_t)(arow * 64 + kq * 2));
        ag_src[p] = A + (size_t)(rb + arow) * lda + kq;
    }
    const char* bbase = (const char*)Wslots;

    float acc[4][4][4];
    #pragma unroll
    for (int i = 0; i < 4; i++)
        #pragma unroll
        for (int j = 0; j < 4; j++)
            #pragma unroll
            for (int r = 0; r < 4; r++) acc[i][j][r] = 0.f;

    auto issue = [&](int buf, int c) {
        uint32_t st = sbase + buf * STAGE_B;
        #pragma unroll
        for (int p = 0; p < 2; p++)
            cpa16(st + OA + ag_sw[p], ag_src[p] + c * KCH);
        // B slot: 8KB straight copy (pre-swizzled)
        const char* bs = bbase + (size_t)c * 8192;
        #pragma unroll
        for (int p = 0; p < 2; p++) {
            uint32_t off = (uint32_t)((p * 256 + tid) * 16);
            cpa16(st + OB + off, bs + off);
        }
    };

    issue(0, 0);
    cp_commit();
    if (nchunks > 1) { issue(1, 1); cp_commit(); }

    for (int c = 0; c < nchunks; c++) {
        if (c + 1 < nchunks) cp_wait1(); else cp_wait0();
        __syncthreads();
        if (c + 2 < nchunks) { issue((c + 2) % NSTAGE, c + 2); cp_commit(); }

        uint32_t st = sbase + (c % NSTAGE) * STAGE_B;
        #pragma unroll
        for (int k16 = 0; k16 < 2; k16++) {
            int kbase = k16 * 16 + kk_off;
            // B fragments
            uint32_t bh[4][2];
            #pragma unroll
            for (int in2 = 0; in2 < 2; in2++) {
                int nrow = wn * 32 + in2 * 16 + row_off;
                uint32_t off = sw64((uint32_t)(nrow * 64 + kbase * 2));
                uint32_t t[4];
                ldm4(t, st + OB + off);
                bh[in2 * 2 + 0][0] = t[0]; bh[in2 * 2 + 0][1] = t[2];
                bh[in2 * 2 + 1][0] = t[1]; bh[in2 * 2 + 1][1] = t[3];
            }
            // A fragments
            uint32_t af[4][4];
            #pragma unroll
            for (int im = 0; im < 4; im++) {
                int mrow = wm * 64 + im * 16 + row_off;
                ldm4(af[im], st + OA + sw64((uint32_t)(mrow * 64 + kbase * 2)));
            }
            #pragma unroll
            for (int im = 0; im < 4; im++)
                #pragma unroll
                for (int in = 0; in < 4; in++)
                    mma16816h(acc[im][in], af[im], bh[in]);
        }
        __syncthreads();
    }

    // ---- epilogue ----
    int r_in = lane >> 2;
    int c_in = (lane & 3) * 2;

    if (EPI == 0 || EPI == 1) {
        #pragma unroll
        for (int im = 0; im < 4; im++) {
            size_t gr0 = (size_t)(rb + wm * 64 + im * 16 + r_in);
            #pragma unroll
            for (int in = 0; in < 4; in++) {
                int cl = wn * 32 + in * 8 + c_in;
                float b0 = bias[cl], b1 = bias[cl + 1];
                float v0 = acc[im][in][0] + b0, v1 = acc[im][in][1] + b1;
                float v2 = acc[im][in][2] + b0, v3 = acc[im][in][3] + b1;
                if (EPI == 1) {
                    v0 = fmaxf(v0, 0.f); v1 = fmaxf(v1, 0.f);
                    v2 = fmaxf(v2, 0.f); v3 = fmaxf(v3, 0.f);
                }
                *(uint32_t*)&Sh[gr0 * lds + ncoloff + cl] = pack_h2(v0, v1);
                *(uint32_t*)&Sh[(gr0 + 8) * lds + ncoloff + cl] = pack_h2(v2, v3);
            }
        }
    } else {
        float sv[4][2] = {}, qv[4][2] = {};
        #pragma unroll
        for (int im = 0; im < 4; im++) {
            size_t gr0 = (size_t)(rb + wm * 64 + im * 16 + r_in);
            #pragma unroll
            for (int in = 0; in < 4; in++) {
                int cl = wn * 32 + in * 8 + c_in;
                float b0 = bias[cl], b1 = bias[cl + 1];
                float2 rv0 = *(const float2*)(R + gr0 * DIM + cl);
                float2 rv1 = *(const float2*)(R + (gr0 + 8) * DIM + cl);
                float v0 = acc[im][in][0] + b0 + rv0.x;
                float v1 = acc[im][in][1] + b1 + rv0.y;
                float v2 = acc[im][in][2] + b0 + rv1.x;
                float v3 = acc[im][in][3] + b1 + rv1.y;
                acc[im][in][0] = v0; acc[im][in][1] = v1;
                acc[im][in][2] = v2; acc[im][in][3] = v3;
                sv[im][0] += v0 + v1; qv[im][0] += v0 * v0 + v1 * v1;
                sv[im][1] += v2 + v3; qv[im][1] += v2 * v2 + v3 * v3;
            }
        }
        #pragma unroll
        for (int im = 0; im < 4; im++)
            #pragma unroll
            for (int h2 = 0; h2 < 2; h2++) {
                float s = sv[im][h2], q = qv[im][h2];
                s += __shfl_xor_sync(0xffffffffu, s, 1);
                s += __shfl_xor_sync(0xffffffffu, s, 2);
                q += __shfl_xor_sync(0xffffffffu, q, 1);
                q += __shfl_xor_sync(0xffffffffu, q, 2);
                if ((lane & 3) == 0) {
                    int rl = wm * 64 + im * 16 + r_in + h2 * 8;
                    s_sp[rl][wn] = s;
                    s_sq[rl][wn] = q;
                }
            }
        __syncthreads();
        float mn[4][2], rs[4][2];
        #pragma unroll
        for (int im = 0; im < 4; im++)
            #pragma unroll
            for (int h2 = 0; h2 < 2; h2++) {
                int rl = wm * 64 + im * 16 + r_in + h2 * 8;
                float s = s_sp[rl][0] + s_sp[rl][1] + s_sp[rl][2] + s_sp[rl][3];
                float q = s_sq[rl][0] + s_sq[rl][1] + s_sq[rl][2] + s_sq[rl][3];
                float m = s * (1.f / 128.f);
                float var = q * (1.f / 128.f) - m * m;
                mn[im][h2] = m;
                rs[im][h2] = rsqrtf(var + EPSV);
            }
        #pragma unroll
        for (int im = 0; im < 4; im++) {
            size_t gr0 = (size_t)(rb + wm * 64 + im * 16 + r_in);
            #pragma unroll
            for (int in = 0; in < 4; in++) {
                int cl = wn * 32 + in * 8 + c_in;
                float g0 = gam[cl], g1 = gam[cl + 1];
                float e0 = bet[cl], e1 = bet[cl + 1];
                float o0 = (acc[im][in][0] - mn[im][0]) * rs[im][0] * g0 + e0;
                float o1 = (acc[im][in][1] - mn[im][0]) * rs[im][0] * g1 + e1;
                float o2 = (acc[im][in][2] - mn[im][1]) * rs[im][1] * g0 + e0;
                float o3 = (acc[im][in][3] - mn[im][1]) * rs[im][1] * g1 + e1;
                *(float2*)(C + gr0 * ldc + cl) = make_float2(o0, o1);
                *(float2*)(C + (gr0 + 8) * ldc + cl) = make_float2(o2, o3);
                *(uint32_t*)&Sh[gr0 * lds + cl] = pack_h2(o0, o1);
                *(uint32_t*)&Sh[(gr0 + 8) * lds + cl] = pack_h2(o2, o3);
            }
        }
    }
}

// Generic GEMM kernel: blockIdx.x = col block, blockIdx.y = row block (128)
template <int EPI>
__global__ __launch_bounds__(256, 2) void gemm_cp_kernel(
    int absel, int lda, int slotbase, int kchunks,
    const float* __restrict__ bias, int rsel,
    const float* __restrict__ gam, const float* __restrict__ bet,
    int csel, int ldc, int ssel, int lds)
{
    extern __shared__ char dsm[];
    int nb = blockIdx.x;
    int rb = blockIdx.y * 128;
    const __half* Ah = selh(absel);
    __half* Sh = selh(ssel);
    const __half* Ws =
        g_Wt + ((size_t)slotbase + (size_t)nb * kchunks) * SLOT_ELE;
    gemm_cp_core<EPI>(dsm, Ah, lda, Ws, kchunks,
                      bias + nb * 128,
                      rsel >= 0 ? self32(rsel) : nullptr, gam, bet,
                      csel >= 0 ? self32(csel) : nullptr, ldc,
                      Sh, lds, nb * 128, rb);
}

// QKV fused: blockIdx.x selects q/k/v (co-scheduled -> A L2 reuse)
__global__ __launch_bounds__(256, 2) void qkv_cp_kernel(
    int lslot, const float* __restrict__ bq,
    const float* __restrict__ bk, const float* __restrict__ bv)
{
    extern __shared__ char dsm[];
    int which = blockIdx.x;
    int rb = blockIdx.y * 128;
    const __half* Ws = g_Wt + (size_t)(lslot + which * 4) * SLOT_ELE;
    const float* bias = (which == 0) ? bq : (which == 1) ? bk : bv;
    __half* Sh = (which == 0) ? g_Qh : (which == 1) ? g_Kh : g_Vh;
    gemm_cp_core<0>(dsm, g_Xs, DIM, Ws, 4, bias,
                    nullptr, nullptr, nullptr, nullptr, 0,
                    Sh, DIM, 0, rb);
}

// ---------------------------------------------------------------------------
// Attention: one warp per 16x16 unit; fp16 in (g_Qh/g_Kh/g_Vh), fp16 out (g_Cs)
// ---------------------------------------------------------------------------
__global__ __launch_bounds__(256) void attn_kernel() {
    __shared__ float s_q[8][256];
    __shared__ float s_k[8][256];
    __shared__ float s_v[8][256];

    int w = threadIdx.x >> 5, lane = threadIdx.x & 31;
    size_t n = (size_t)blockIdx.x * 8 + w;
    size_t bse = n * 256;

    // each lane: one uint4 (8 halves) per tensor
    {
        uint4 qv = *(const uint4*)(g_Qh + bse + lane * 8);
        uint4 kv = *(const uint4*)(g_Kh + bse + lane * 8);
        uint4 vv = *(const uint4*)(g_Vh + bse + lane * 8);
        const uint32_t* qp = (const uint32_t*)&qv;
        const uint32_t* kp = (const uint32_t*)&kv;
        const uint32_t* vp = (const uint32_t*)&vv;
        #pragma unroll
        for (int u = 0; u < 4; u++) {
            float2 f;
            f = __half22float2(*(const __half2*)&qp[u]);
            s_q[w][lane * 8 + u * 2] = f.x; s_q[w][lane * 8 + u * 2 + 1] = f.y;
            f = __half22float2(*(const __half2*)&kp[u]);
            s_k[w][lane * 8 + u * 2] = f.x; s_k[w][lane * 8 + u * 2 + 1] = f.y;
            f = __half22float2(*(const __half2*)&vp[u]);
            s_v[w][lane * 8 + u * 2] = f.x; s_v[w][lane * 8 + u * 2 + 1] = f.y;
        }
    }
    __syncwarp();

    int i = lane >> 1;
    int jb = (lane & 1) * 8;

    float qr[16];
    #pragma unroll
    for (int u = 0; u < 4; u++) {
        float4 t4 = *(const float4*)&s_q[w][i * 16 + u * 4];
        qr[u * 4 + 0] = t4.x; qr[u * 4 + 1] = t4.y;
        qr[u * 4 + 2] = t4.z; qr[u * 4 + 3] = t4.w;
    }

    float sc[8];
    #pragma unroll
    for (int j = 0; j < 8; j++) {
        const float* kr = &s_k[w][(jb + j) * 16];
        float dd = 0.f;
        #pragma unroll
        for (int u = 0; u < 16; u++) dd = fmaf(qr[u], kr[u], dd);
        sc[j] = dd * 0.25f;
    }

    float mx = sc[0];
    #pragma unroll
    for (int j = 1; j < 8; j++) mx = fmaxf(mx, sc[j]);
    mx = fmaxf(mx, __shfl_xor_sync(0xffffffffu, mx, 1));

    float sum = 0.f;
    #pragma unroll
    for (int j = 0; j < 8; j++) { sc[j] = __expf(sc[j] - mx); sum += sc[j]; }
    sum += __shfl_xor_sync(0xffffffffu, sum, 1);
    float inv = 1.f / sum;

    float acc[16] = {};
    #pragma unroll
    for (int j = 0; j < 8; j++) {
        float p = sc[j] * inv;
        const float* vr = &s_v[w][(jb + j) * 16];
        #pragma unroll
        for (int u = 0; u < 16; u++) acc[u] = fmaf(p, vr[u], acc[u]);
    }
    #pragma unroll
    for (int u = 0; u < 16; u++)
        acc[u] += __shfl_xor_sync(0xffffffffu, acc[u], 1);

    int db = (lane & 1) * 8;
    size_t e = bse + i * 16 + db;
    *(uint4*)(&g_Cs[e]) = make_uint4(
        pack_h2(acc[db + 0], acc[db + 1]), pack_h2(acc[db + 2], acc[db + 3]),
        pack_h2(acc[db + 4], acc[db + 5]), pack_h2(acc[db + 6], acc[db + 7]));
}

// ---------------------------------------------------------------------------
// Head
// ---------------------------------------------------------------------------
__global__ __launch_bounds__(128) void numproj_kernel(
    const float* __restrict__ num, const float* __restrict__ Wn,
    const float* __restrict__ bnum)
{
    __shared__ float sn[NUMF];
    int b = blockIdx.x, t = threadIdx.x;
    if (t < NUMF) sn[t] = num[(size_t)b * NUMF + t];
    __syncthreads();
    float acc = bnum[t];
    #pragma unroll 1
    for (int k = 0; k < NUMF; k++)
        acc = fmaf(sn[k], Wn[k * DIM + t], acc);
    g_Np[(size_t)b * DIM + t] = acc;
}

__global__ __launch_bounds__(256) void bn_partial_kernel() {
    int j = blockIdx.x, t = threadIdx.x;
    int col = t & 127, half = t >> 7;
    float s = 0.f, q = 0.f;
    for (int i = 0; i < 64; i++) {
        float v = g_Np[(size_t)(j * 128 + half * 64 + i) * DIM + col];
        s += v; q += v * v;
    }
    __shared__ float ss[256], sq[256];
    ss[t] = s; sq[t] = q;
    __syncthreads();
    if (half == 0) {
        g_bnp[j * DIM + col]            = ss[t] + ss[t + 128];
        g_bnp[64 * DIM + j * DIM + col] = sq[t] + sq[t + 128];
    }
}

__global__ __launch_bounds__(128) void bn_final_kernel(
    const float* __restrict__ gamma, const float* __restrict__ beta)
{
    int c = threadIdx.x;
    float s = 0.f, q = 0.f;
    for (int j = 0; j < 64; j++) {
        s += g_bnp[j * DIM + c];
        q += g_bnp[64 * DIM + j * DIM + c];
    }
    float mu = s * (1.f / 8192.f);
    float var = q * (1.f / 8192.f) - mu * mu;
    float a = gamma[c] * rsqrtf(var + EPSV);
    g_bns[c] = a;
    g_bns[DIM + c] = beta[c] - mu * a;
}

__global__ __launch_bounds__(256) void final_kernel(
    const float* __restrict__ gcn, const float* __restrict__ Wf,
    const float* __restrict__ bf, float* __restrict__ out)
{
    int b = blockIdx.x, t = threadIdx.x;
    const float* xr = g_X + (size_t)b * (SEQ * DIM);
    float acc = 0.f;
    #pragma unroll
    for (int i = 0; i < 8; i++) {
        int idx = t + 256 * i;
        acc = fmaf(xr[idx], Wf[idx], acc);
    }
    if (t < GCN)
        acc = fmaf(gcn[(size_t)b * GCN + t], Wf[SEQ * DIM + t], acc);
    if (t < DIM) {
        float v = g_Np[(size_t)b * DIM + t] * g_bns[t] + g_bns[DIM + t];
        acc = fmaf(v, Wf[SEQ * DIM + GCN + t], acc);
    }
    acc = warp_red(acc);
    __shared__ float red[8];
    if ((t & 31) == 0) red[t >> 5] = acc;
    __syncthreads();
    if (t == 0) {
        float z = red[0] + red[1] + red[2] + red[3]
                + red[4] + red[5] + red[6] + red[7] + bf[0];
        out[b] = 1.f / (1.f + expf(-z));
    }
}

// ---------------------------------------------------------------------------
// Launch
// ---------------------------------------------------------------------------
extern "C" void kernel_launch(void* const* d_in, const int* in_sizes, int n_in,
                              void* d_out, int out_size)
{
    const float* x    = (const float*)d_in[0];
    const float* gcn  = (const float*)d_in[1];
    const float* num  = (const float*)d_in[2];
    const float* Wq   = (const float*)d_in[3];
    const float* bq   = (const float*)d_in[4];
    const float* Wk   = (const float*)d_in[5];
    const float* bk   = (const float*)d_in[6];
    const float* Wv   = (const float*)d_in[7];
    const float* bv   = (const float*)d_in[8];
    const float* Wo   = (const float*)d_in[9];
    const float* bo   = (const float*)d_in[10];
    const float* ln1g = (const float*)d_in[11];
    const float* ln1b = (const float*)d_in[12];
    const float* W1   = (const float*)d_in[13];
    const float* b1   = (const float*)d_in[14];
    const float* W2   = (const float*)d_in[15];
    const float* b2   = (const float*)d_in[16];
    const float* ln2g = (const float*)d_in[17];
    const float* ln2b = (const float*)d_in[18];
    const float* Wn   = (const float*)d_in[19];
    const float* bnum = (const float*)d_in[20];
    const float* bng  = (const float*)d_in[21];
    const float* bnb  = (const float*)d_in[22];
    const float* Wf   = (const float*)d_in[23];
    const float* bf   = (const float*)d_in[24];
    float* out = (float*)d_out;

    cudaFuncSetAttribute(qkv_cp_kernel,
        cudaFuncAttributeMaxDynamicSharedMemorySize, DSMEM_BYTES);
    cudaFuncSetAttribute(gemm_cp_kernel<1>,
        cudaFuncAttributeMaxDynamicSharedMemorySize, DSMEM_BYTES);
    cudaFuncSetAttribute(gemm_cp_kernel<2>,
        cudaFuncAttributeMaxDynamicSharedMemorySize, DSMEM_BYTES);

    pe_init_kernel<<<2, 1024>>>();
    prep_weights_kernel<<<SLOTS_TOTAL, 256>>>(Wq, Wk, Wv, Wo, W1, W2);
    add_pe_kernel<<<16384, 256>>>(x);

    const int RB = MTOT / 128;   // 1024 row blocks
    for (int l = 0; l < 2; l++) {
        int lb = l * 80;
        // QKV: g_Xs -> Qh,Kh,Vh (fp16)
        qkv_cp_kernel<<<dim3(3, RB), 256, DSMEM_BYTES>>>(
            lb, bq + l * DIM, bk + l * DIM, bv + l * DIM);
        // attention: fp16 q,k,v -> ctx fp16 (g_Cs)
        attn_kernel<<<MTOT / 16, 256>>>();
        // h = LN(ctx @ Wo + bo + X): fp32 -> g_Kb, fp16 -> g_Hs
        gemm_cp_kernel<2><<<dim3(1, RB), 256, DSMEM_BYTES>>>(
            1, DIM, lb + 12, 4, bo + l * DIM, 0,
            ln1g + l * DIM, ln1b + l * DIM, 2, DIM, 2, DIM);
        // ffn hidden = relu(h @ W1 + b1): fp16 -> g_Fs
        gemm_cp_kernel<1><<<dim3(8, RB), 256, DSMEM_BYTES>>>(
            2, DIM, lb + 16, 4, b1 + l * HID, -1,
            nullptr, nullptr, -1, 0, 3, HID);
        // out = LN(ffn @ W2 + b2 + h): fp32 -> g_X, fp16 -> g_Xs
        gemm_cp_kernel<2><<<dim3(1, RB), 256, DSMEM_BYTES>>>(
            3, HID, lb + 48, 32, b2 + l * DIM, 2,
            ln2g + l * DIM, ln2b + l * DIM, 0, DIM, 0, DIM);
    }

    numproj_kernel<<<BATCH, 128>>>(num, Wn, bnum);
    bn_partial_kernel<<<64, 256>>>();
    bn_final_kernel<<<1, 128>>>(bng, bnb);
    final_kernel<<<BATCH, 256>>>(gcn, Wf, bf, out);
}